// round 1
// baseline (speedup 1.0000x reference)
#include <cuda_runtime.h>
#include <cuda_bf16.h>
#include <math.h>

// Problem constants
#define B_   2
#define T_   2048
#define E_   2048
#define H_   16
#define HKV_ 4
#define D_   128
#define ROWS (B_ * T_)          // 4096
#define QCOLS (H_ * D_)         // 2048
#define KCOLS (HKV_ * D_)       // 512

// Scratch (allocation-free: device globals)
__device__ float g_Q[(size_t)ROWS * QCOLS];
__device__ float g_K[(size_t)ROWS * KCOLS];
__device__ float g_V[(size_t)ROWS * KCOLS];
__device__ float g_ctx[(size_t)ROWS * QCOLS];

// ---------------------------------------------------------------------------
// Classic 128x128x8 SGEMM, 256 threads, 8x8 per-thread micro-tile.
// A[M,K] row-major, B[K,N] row-major, C[M,N] row-major. M%128==0, N%128==0, K%8==0.
// ---------------------------------------------------------------------------
__global__ __launch_bounds__(256) void sgemm128(const float* __restrict__ A,
                                                const float* __restrict__ Bm,
                                                float* __restrict__ C,
                                                int M, int N, int K) {
    __shared__ float As[8][128];
    __shared__ float Bs[8][128];

    const int bm = blockIdx.y * 128;
    const int bn = blockIdx.x * 128;
    const int tid = threadIdx.x;
    const int tm = tid >> 4;          // 0..15
    const int tn = tid & 15;          // 0..15

    const int arow = tid >> 1;        // 0..127
    const int acol = (tid & 1) * 4;   // 0 or 4
    const int brow = tid >> 5;        // 0..7
    const int bcol = (tid & 31) * 4;  // 0..124

    const float* Aptr = A + (size_t)(bm + arow) * K + acol;
    const float* Bptr = Bm + (size_t)brow * N + bn + bcol;

    float acc[8][8];
#pragma unroll
    for (int i = 0; i < 8; i++)
#pragma unroll
        for (int j = 0; j < 8; j++) acc[i][j] = 0.f;

    for (int k0 = 0; k0 < K; k0 += 8) {
        float4 a4 = *(const float4*)Aptr;  Aptr += 8;
        float4 b4 = *(const float4*)Bptr;  Bptr += (size_t)8 * N;

        As[acol + 0][arow] = a4.x;
        As[acol + 1][arow] = a4.y;
        As[acol + 2][arow] = a4.z;
        As[acol + 3][arow] = a4.w;
        *(float4*)&Bs[brow][bcol] = b4;
        __syncthreads();

#pragma unroll
        for (int k = 0; k < 8; k++) {
            float ra[8], rb[8];
            *(float4*)&ra[0] = *(const float4*)&As[k][tm * 8];
            *(float4*)&ra[4] = *(const float4*)&As[k][tm * 8 + 4];
            *(float4*)&rb[0] = *(const float4*)&Bs[k][tn * 8];
            *(float4*)&rb[4] = *(const float4*)&Bs[k][tn * 8 + 4];
#pragma unroll
            for (int i = 0; i < 8; i++)
#pragma unroll
                for (int j = 0; j < 8; j++)
                    acc[i][j] = fmaf(ra[i], rb[j], acc[i][j]);
        }
        __syncthreads();
    }

#pragma unroll
    for (int i = 0; i < 8; i++) {
        float* crow = C + (size_t)(bm + tm * 8 + i) * N + bn + tn * 8;
        *(float4*)crow       = make_float4(acc[i][0], acc[i][1], acc[i][2], acc[i][3]);
        *(float4*)(crow + 4) = make_float4(acc[i][4], acc[i][5], acc[i][6], acc[i][7]);
    }
}

// ---------------------------------------------------------------------------
// RoPE in-place on [ROWS, nheads*128] matrix. Pairs are adjacent (2i, 2i+1).
// angle = t * base^(-i/64). Double-precision tables (cheap, removes the
// transcendental-accuracy term from the error budget).
// ---------------------------------------------------------------------------
__global__ void rope_kernel(float* __restrict__ X, int nheads, int total) {
    int idx = blockIdx.x * blockDim.x + threadIdx.x;
    if (idx >= total) return;
    const int pairs_per_row = nheads * 64;
    int row = idx / pairs_per_row;
    int p   = idx - row * pairs_per_row;
    int h = p >> 6;
    int i = p & 63;
    int t = row & (T_ - 1);

    double w = pow(10000.0, -(double)i / 64.0);
    double ang = (double)t * w;
    double ds, dc;
    sincos(ang, &ds, &dc);
    float s = (float)ds, c = (float)dc;

    float* base = X + (size_t)row * (nheads * 128) + h * 128 + 2 * i;
    float re = base[0], im = base[1];
    base[0] = re * c - im * s;
    base[1] = re * s + im * c;
}

// ---------------------------------------------------------------------------
// Causal flash attention, fp32. BLOCK_M = BLOCK_N = 64, D = 128.
// 256 threads as a 16x16 grid; each thread owns a 4(row) x [4 score / 8 out]
// micro-tile. Online softmax with per-row redundant (m, l) in registers.
// grid = (T/64, H, B)
// ---------------------------------------------------------------------------
#define FA_SMEM_FLOATS (128*68 + 128*68 + 64*132 + 64*68)
__global__ __launch_bounds__(256) void flash_kernel(const float* __restrict__ Q,
                                                    const float* __restrict__ Km,
                                                    const float* __restrict__ Vm,
                                                    float* __restrict__ ctx) {
    const float SCALE = 0.08838834764831845f;  // 1/sqrt(128)
    const int m0  = blockIdx.x * 64;
    const int h   = blockIdx.y;
    const int b   = blockIdx.z;
    const int kvh = h >> 2;  // H/HKV = 4

    extern __shared__ float smf[];
    float* QsT = smf;                    // [128][68]  (d-major)
    float* KsT = QsT + 128 * 68;         // [128][68]
    float* Vs  = KsT + 128 * 68;         // [64][132]  (key-major)
    float* Ps  = Vs  + 64 * 132;         // [64][68]

    const int tid = threadIdx.x;
    const int tm = tid >> 4;   // 0..15
    const int tn = tid & 15;   // 0..15
    const int row0 = tm * 4;   // local query rows row0..row0+3

    // Load Q tile transposed into shared
    {
        const float* qbase = Q + (size_t)(b * T_ + m0) * QCOLS + h * 128;
        for (int i = tid; i < 64 * 32; i += 256) {
            int r = i >> 5, d = (i & 31) << 2;
            float4 v = *(const float4*)(qbase + (size_t)r * QCOLS + d);
            QsT[(d + 0) * 68 + r] = v.x;
            QsT[(d + 1) * 68 + r] = v.y;
            QsT[(d + 2) * 68 + r] = v.z;
            QsT[(d + 3) * 68 + r] = v.w;
        }
    }

    float acc[4][8];
    float m_i[4], l_i[4];
#pragma unroll
    for (int i = 0; i < 4; i++) {
        m_i[i] = -1e30f;
        l_i[i] = 0.f;
#pragma unroll
        for (int c = 0; c < 8; c++) acc[i][c] = 0.f;
    }
    __syncthreads();

    for (int n0 = 0; n0 <= m0; n0 += 64) {
        // Load K (transposed) and V tiles
        {
            const float* kbase = Km + (size_t)(b * T_ + n0) * KCOLS + kvh * 128;
            const float* vbase = Vm + (size_t)(b * T_ + n0) * KCOLS + kvh * 128;
            for (int i = tid; i < 64 * 32; i += 256) {
                int r = i >> 5, d = (i & 31) << 2;
                float4 kk = *(const float4*)(kbase + (size_t)r * KCOLS + d);
                KsT[(d + 0) * 68 + r] = kk.x;
                KsT[(d + 1) * 68 + r] = kk.y;
                KsT[(d + 2) * 68 + r] = kk.z;
                KsT[(d + 3) * 68 + r] = kk.w;
                float4 vv = *(const float4*)(vbase + (size_t)r * KCOLS + d);
                *(float4*)&Vs[r * 132 + d] = vv;
            }
        }
        __syncthreads();

        // S = Q K^T for this thread's 4x4 sub-tile
        float s[4][4];
#pragma unroll
        for (int i = 0; i < 4; i++)
#pragma unroll
            for (int j = 0; j < 4; j++) s[i][j] = 0.f;

#pragma unroll 4
        for (int k = 0; k < 128; k++) {
            float qa[4], kb[4];
            *(float4*)qa = *(const float4*)&QsT[k * 68 + row0];
            *(float4*)kb = *(const float4*)&KsT[k * 68 + (tn << 2)];
#pragma unroll
            for (int i = 0; i < 4; i++)
#pragma unroll
                for (int j = 0; j < 4; j++)
                    s[i][j] = fmaf(qa[i], kb[j], s[i][j]);
        }

        // scale + causal mask + local row max
        float rmax[4];
#pragma unroll
        for (int i = 0; i < 4; i++) {
            int qi = m0 + row0 + i;
            rmax[i] = -1e30f;
#pragma unroll
            for (int j = 0; j < 4; j++) {
                int kj = n0 + (tn << 2) + j;
                float sv = (kj <= qi) ? s[i][j] * SCALE : -1e30f;
                s[i][j] = sv;
                rmax[i] = fmaxf(rmax[i], sv);
            }
        }
        // reduce max over the 16-lane tn group
#pragma unroll
        for (int ofs = 8; ofs; ofs >>= 1)
#pragma unroll
            for (int i = 0; i < 4; i++)
                rmax[i] = fmaxf(rmax[i], __shfl_xor_sync(0xffffffffu, rmax[i], ofs));

        float mnew[4], alpha[4], rsum[4];
#pragma unroll
        for (int i = 0; i < 4; i++) {
            mnew[i]  = fmaxf(m_i[i], rmax[i]);
            alpha[i] = __expf(m_i[i] - mnew[i]);
            float rs = 0.f;
#pragma unroll
            for (int j = 0; j < 4; j++) {
                float p = __expf(s[i][j] - mnew[i]);
                Ps[(row0 + i) * 68 + (tn << 2) + j] = p;
                rs += p;
            }
            rsum[i] = rs;
        }
#pragma unroll
        for (int ofs = 8; ofs; ofs >>= 1)
#pragma unroll
            for (int i = 0; i < 4; i++)
                rsum[i] += __shfl_xor_sync(0xffffffffu, rsum[i], ofs);
#pragma unroll
        for (int i = 0; i < 4; i++) {
            l_i[i] = l_i[i] * alpha[i] + rsum[i];
            m_i[i] = mnew[i];
#pragma unroll
            for (int c = 0; c < 8; c++) acc[i][c] *= alpha[i];
        }
        __syncthreads();   // Ps visible to everyone

        // O += P @ V
#pragma unroll 2
        for (int j = 0; j < 64; j++) {
            float p0 = Ps[(row0 + 0) * 68 + j];
            float p1 = Ps[(row0 + 1) * 68 + j];
            float p2 = Ps[(row0 + 2) * 68 + j];
            float p3 = Ps[(row0 + 3) * 68 + j];
            float v[8];
            *(float4*)&v[0] = *(const float4*)&Vs[j * 132 + (tn << 3)];
            *(float4*)&v[4] = *(const float4*)&Vs[j * 132 + (tn << 3) + 4];
#pragma unroll
            for (int c = 0; c < 8; c++) {
                acc[0][c] = fmaf(p0, v[c], acc[0][c]);
                acc[1][c] = fmaf(p1, v[c], acc[1][c]);
                acc[2][c] = fmaf(p2, v[c], acc[2][c]);
                acc[3][c] = fmaf(p3, v[c], acc[3][c]);
            }
        }
        __syncthreads();   // before next tile overwrites K/V/P
    }

    // epilogue: normalize and store into ctx (b, t, h*128 + d)
#pragma unroll
    for (int i = 0; i < 4; i++) {
        float inv = 1.0f / l_i[i];
        float* cdst = ctx + (size_t)(b * T_ + m0 + row0 + i) * QCOLS + h * 128 + (tn << 3);
        *(float4*)cdst       = make_float4(acc[i][0] * inv, acc[i][1] * inv,
                                           acc[i][2] * inv, acc[i][3] * inv);
        *(float4*)(cdst + 4) = make_float4(acc[i][4] * inv, acc[i][5] * inv,
                                           acc[i][6] * inv, acc[i][7] * inv);
    }
}

// ---------------------------------------------------------------------------
extern "C" void kernel_launch(void* const* d_in, const int* in_sizes, int n_in,
                              void* d_out, int out_size) {
    const float* x    = (const float*)d_in[0];
    const float* Wq   = (const float*)d_in[1];
    const float* Wk   = (const float*)d_in[2];
    const float* Wv   = (const float*)d_in[3];
    const float* Wout = (const float*)d_in[4];
    float* out = (float*)d_out;

    float *Qb, *Kb, *Vb, *Cb;
    cudaGetSymbolAddress((void**)&Qb, g_Q);
    cudaGetSymbolAddress((void**)&Kb, g_K);
    cudaGetSymbolAddress((void**)&Vb, g_V);
    cudaGetSymbolAddress((void**)&Cb, g_ctx);

    const size_t fa_smem = (size_t)FA_SMEM_FLOATS * sizeof(float);
    cudaFuncSetAttribute(flash_kernel, cudaFuncAttributeMaxDynamicSharedMemorySize,
                         (int)fa_smem);

    // Projections
    sgemm128<<<dim3(QCOLS / 128, ROWS / 128), 256>>>(x, Wq, Qb, ROWS, QCOLS, E_);
    sgemm128<<<dim3(KCOLS / 128, ROWS / 128), 256>>>(x, Wk, Kb, ROWS, KCOLS, E_);
    sgemm128<<<dim3(KCOLS / 128, ROWS / 128), 256>>>(x, Wv, Vb, ROWS, KCOLS, E_);

    // RoPE on Q and K
    {
        int totq = ROWS * H_ * 64;
        rope_kernel<<<(totq + 255) / 256, 256>>>(Qb, H_, totq);
        int totk = ROWS * HKV_ * 64;
        rope_kernel<<<(totk + 255) / 256, 256>>>(Kb, HKV_, totk);
    }

    // Attention
    flash_kernel<<<dim3(T_ / 64, H_, B_), 256, fa_smem>>>(Qb, Kb, Vb, Cb);

    // Output projection
    sgemm128<<<dim3(E_ / 128, ROWS / 128), 256>>>(Cb, Wout, out, ROWS, E_, QCOLS);
}

// round 3
// speedup vs baseline: 1.8019x; 1.8019x over previous
#include <cuda_runtime.h>
#include <cuda_bf16.h>
#include <math.h>
#include <stdint.h>

// Problem constants
#define B_   2
#define T_   2048
#define E_   2048
#define H_   16
#define HKV_ 4
#define D_   128
#define ROWS (B_ * T_)          // 4096
#define QCOLS (H_ * D_)         // 2048
#define KCOLS (HKV_ * D_)       // 512

// ---------------------------------------------------------------------------
// Scratch (allocation-free: device globals)
// ---------------------------------------------------------------------------
__device__ __align__(1024) float g_xr [(size_t)ROWS * E_];      // tf32-rounded x
__device__ __align__(1024) float g_Wq [(size_t)E_ * QCOLS];     // rounded weights (orig layout)
__device__ __align__(1024) float g_Wk [(size_t)E_ * KCOLS];
__device__ __align__(1024) float g_Wv [(size_t)E_ * KCOLS];
__device__ __align__(1024) float g_Wo [(size_t)QCOLS * E_];
__device__ __align__(1024) float g_Q  [(size_t)ROWS * QCOLS];
__device__ __align__(1024) float g_K  [(size_t)ROWS * KCOLS];
__device__ __align__(1024) float g_V  [(size_t)ROWS * KCOLS];
__device__ __align__(1024) float g_ctx[(size_t)ROWS * QCOLS];

// ---------------------------------------------------------------------------
// Helpers
// ---------------------------------------------------------------------------
__device__ __forceinline__ float rna_tf32(float x) {
    uint32_t y;
    asm("cvt.rna.tf32.f32 %0, %1;" : "=r"(y) : "f"(x));
    return __uint_as_float(y);
}
__device__ __forceinline__ uint32_t smem_u32(const void* p) {
    uint32_t a;
    asm("{ .reg .u64 t; cvta.to.shared.u64 t, %1; cvt.u32.u64 %0, t; }" : "=r"(a) : "l"(p));
    return a;
}
__device__ __forceinline__ void cp_async16(uint32_t saddr, const void* gptr) {
    asm volatile("cp.async.cg.shared.global [%0], [%1], 16;" :: "r"(saddr), "l"(gptr));
}
#define CP_COMMIT() asm volatile("cp.async.commit_group;" ::: "memory")
#define CP_WAIT(n)  asm volatile("cp.async.wait_group %0;" :: "n"(n) : "memory")

__device__ __forceinline__ void mma_tf32(float* c, const uint32_t* a, const uint32_t* b) {
    asm volatile(
        "mma.sync.aligned.m16n8k8.row.col.f32.tf32.tf32.f32 "
        "{%0,%1,%2,%3}, {%4,%5,%6,%7}, {%8,%9}, {%0,%1,%2,%3};"
        : "+f"(c[0]), "+f"(c[1]), "+f"(c[2]), "+f"(c[3])
        : "r"(a[0]), "r"(a[1]), "r"(a[2]), "r"(a[3]), "r"(b[0]), "r"(b[1]));
}

// ---------------------------------------------------------------------------
// TF32 mma.sync GEMM: C[M,N] = A[M,K] @ B[K,N], all row-major, tf32-rounded in.
// Tile 128x128x32, 3-stage cp.async pipeline, 256 threads (8 warps, 4x2).
// Warp tile 32x64. Requires M%128==0, N%128==0, K%32==0.
// ---------------------------------------------------------------------------
#define GBM 128
#define GBN 128
#define GBK 32
#define GAST 36         // As stride (floats): conflict-free A frags
#define GBST 136        // Bs stride (floats): conflict-free B frags
#define GSTAGES 3
#define GA_FLOATS (GBM * GAST)      // 4608
#define GB_FLOATS (GBK * GBST)      // 4352
#define GSTAGE_FLOATS (GA_FLOATS + GB_FLOATS)
#define GSMEM_BYTES (GSTAGES * GSTAGE_FLOATS * 4)   // 107520

__global__ __launch_bounds__(256) void gemm_mma(const float* __restrict__ A,
                                                const float* __restrict__ Bw,
                                                float* __restrict__ C,
                                                int M, int N, int K) {
    extern __shared__ __align__(16) float smem[];
    const int tid = threadIdx.x;
    const int wid = tid >> 5, lane = tid & 31;
    const int warpM = wid & 3, warpN = wid >> 2;
    const int m0 = blockIdx.y * GBM, n0 = blockIdx.x * GBN;
    const int nch = K / GBK;

    const int lr = lane >> 2;   // 0..7
    const int lc = lane & 3;    // 0..3

    float acc[2][8][4];
#pragma unroll
    for (int i = 0; i < 2; i++)
#pragma unroll
        for (int j = 0; j < 8; j++)
#pragma unroll
            for (int q = 0; q < 4; q++) acc[i][j][q] = 0.f;

    // cp.async load of chunk c into stage s
    auto load_chunk = [&](int c, int s) {
        float* As = smem + s * GSTAGE_FLOATS;
        float* Bs = As + GA_FLOATS;
        const uint32_t as_base = smem_u32(As);
        const uint32_t bs_base = smem_u32(Bs);
        // A: 128 rows x 8 chunks of 16B
#pragma unroll
        for (int i = 0; i < 4; i++) {
            int ci = tid + i * 256;
            int row = ci >> 3, ch = ci & 7;
            cp_async16(as_base + (row * GAST + ch * 4) * 4,
                       A + (size_t)(m0 + row) * K + c * GBK + ch * 4);
        }
        // B: 32 rows x 32 chunks of 16B
#pragma unroll
        for (int i = 0; i < 4; i++) {
            int ci = tid + i * 256;
            int row = ci >> 5, ch = ci & 31;
            cp_async16(bs_base + (row * GBST + ch * 4) * 4,
                       Bw + (size_t)(c * GBK + row) * N + n0 + ch * 4);
        }
    };

#pragma unroll
    for (int s = 0; s < GSTAGES - 1; s++) { load_chunk(s, s); CP_COMMIT(); }

    for (int c = 0; c < nch; c++) {
        CP_WAIT(GSTAGES - 2);
        __syncthreads();

        int pc = c + GSTAGES - 1;
        if (pc < nch) load_chunk(pc, pc % GSTAGES);
        CP_COMMIT();

        const float* As = smem + (c % GSTAGES) * GSTAGE_FLOATS;
        const float* Bs = As + GA_FLOATS;
        const uint32_t* Asu = (const uint32_t*)As;
        const uint32_t* Bsu = (const uint32_t*)Bs;

#pragma unroll
        for (int kk = 0; kk < 4; kk++) {
            uint32_t afr[2][4], bfr[8][2];
#pragma unroll
            for (int mt = 0; mt < 2; mt++) {
                int row = warpM * 32 + mt * 16 + lr;
                int col = kk * 8 + lc;
                afr[mt][0] = Asu[row * GAST + col];
                afr[mt][1] = Asu[(row + 8) * GAST + col];
                afr[mt][2] = Asu[row * GAST + col + 4];
                afr[mt][3] = Asu[(row + 8) * GAST + col + 4];
            }
#pragma unroll
            for (int nt = 0; nt < 8; nt++) {
                int n = warpN * 64 + nt * 8 + lr;
                int k = kk * 8 + lc;
                bfr[nt][0] = Bsu[k * GBST + n];
                bfr[nt][1] = Bsu[(k + 4) * GBST + n];
            }
#pragma unroll
            for (int mt = 0; mt < 2; mt++)
#pragma unroll
                for (int nt = 0; nt < 8; nt++)
                    mma_tf32(acc[mt][nt], afr[mt], bfr[nt]);
        }
        __syncthreads();
    }

    // Epilogue
#pragma unroll
    for (int mt = 0; mt < 2; mt++) {
        int rbase = m0 + warpM * 32 + mt * 16 + lr;
#pragma unroll
        for (int nt = 0; nt < 8; nt++) {
            int cbase = n0 + warpN * 64 + nt * 8 + lc * 2;
            *(float2*)(C + (size_t)rbase * N + cbase)       = make_float2(acc[mt][nt][0], acc[mt][nt][1]);
            *(float2*)(C + (size_t)(rbase + 8) * N + cbase) = make_float2(acc[mt][nt][2], acc[mt][nt][3]);
        }
    }
}

// ---------------------------------------------------------------------------
// Operand prep: tf32-RN rounding copy (vectorized).
// ---------------------------------------------------------------------------
__global__ void prep_round(const float* __restrict__ in, float* __restrict__ out, int n4) {
    int i = blockIdx.x * blockDim.x + threadIdx.x;
    if (i >= n4) return;
    float4 v = ((const float4*)in)[i];
    v.x = rna_tf32(v.x); v.y = rna_tf32(v.y); v.z = rna_tf32(v.z); v.w = rna_tf32(v.w);
    ((float4*)out)[i] = v;
}

// ---------------------------------------------------------------------------
// RoPE in-place on [ROWS, nheads*128]. Pairs adjacent. Double tables.
// Output re-rounded to tf32 (K feeds only fp32 flash; Q too — harmless).
// ---------------------------------------------------------------------------
__global__ void rope_kernel(float* __restrict__ X, int nheads, int total) {
    int idx = blockIdx.x * blockDim.x + threadIdx.x;
    if (idx >= total) return;
    const int pairs_per_row = nheads * 64;
    int row = idx / pairs_per_row;
    int p   = idx - row * pairs_per_row;
    int h = p >> 6;
    int i = p & 63;
    int t = row & (T_ - 1);

    double w = pow(10000.0, -(double)i / 64.0);
    double ang = (double)t * w;
    double ds, dc;
    sincos(ang, &ds, &dc);
    float s = (float)ds, c = (float)dc;

    float* base = X + (size_t)row * (nheads * 128) + h * 128 + 2 * i;
    float re = base[0], im = base[1];
    base[0] = re * c - im * s;
    base[1] = re * s + im * c;
}

// ---------------------------------------------------------------------------
// Causal flash attention, fp32 (unchanged). ctx stores tf32-RN rounded values
// so the downstream mma.sync GEMM sees properly rounded operands.
// ---------------------------------------------------------------------------
#define FA_SMEM_FLOATS (128*68 + 128*68 + 64*132 + 64*68)
__global__ __launch_bounds__(256) void flash_kernel(const float* __restrict__ Q,
                                                    const float* __restrict__ Km,
                                                    const float* __restrict__ Vm,
                                                    float* __restrict__ ctx) {
    const float SCALE = 0.08838834764831845f;  // 1/sqrt(128)
    const int m0  = blockIdx.x * 64;
    const int h   = blockIdx.y;
    const int b   = blockIdx.z;
    const int kvh = h >> 2;

    extern __shared__ float smf[];
    float* QsT = smf;                    // [128][68]
    float* KsT = QsT + 128 * 68;         // [128][68]
    float* Vs  = KsT + 128 * 68;         // [64][132]
    float* Ps  = Vs  + 64 * 132;         // [64][68]

    const int tid = threadIdx.x;
    const int tm = tid >> 4;
    const int tn = tid & 15;
    const int row0 = tm * 4;

    {
        const float* qbase = Q + (size_t)(b * T_ + m0) * QCOLS + h * 128;
        for (int i = tid; i < 64 * 32; i += 256) {
            int r = i >> 5, d = (i & 31) << 2;
            float4 v = *(const float4*)(qbase + (size_t)r * QCOLS + d);
            QsT[(d + 0) * 68 + r] = v.x;
            QsT[(d + 1) * 68 + r] = v.y;
            QsT[(d + 2) * 68 + r] = v.z;
            QsT[(d + 3) * 68 + r] = v.w;
        }
    }

    float acc[4][8];
    float m_i[4], l_i[4];
#pragma unroll
    for (int i = 0; i < 4; i++) {
        m_i[i] = -1e30f; l_i[i] = 0.f;
#pragma unroll
        for (int c = 0; c < 8; c++) acc[i][c] = 0.f;
    }
    __syncthreads();

    for (int n0 = 0; n0 <= m0; n0 += 64) {
        {
            const float* kbase = Km + (size_t)(b * T_ + n0) * KCOLS + kvh * 128;
            const float* vbase = Vm + (size_t)(b * T_ + n0) * KCOLS + kvh * 128;
            for (int i = tid; i < 64 * 32; i += 256) {
                int r = i >> 5, d = (i & 31) << 2;
                float4 kk = *(const float4*)(kbase + (size_t)r * KCOLS + d);
                KsT[(d + 0) * 68 + r] = kk.x;
                KsT[(d + 1) * 68 + r] = kk.y;
                KsT[(d + 2) * 68 + r] = kk.z;
                KsT[(d + 3) * 68 + r] = kk.w;
                float4 vv = *(const float4*)(vbase + (size_t)r * KCOLS + d);
                *(float4*)&Vs[r * 132 + d] = vv;
            }
        }
        __syncthreads();

        float s[4][4];
#pragma unroll
        for (int i = 0; i < 4; i++)
#pragma unroll
            for (int j = 0; j < 4; j++) s[i][j] = 0.f;

#pragma unroll 4
        for (int k = 0; k < 128; k++) {
            float qa[4], kb[4];
            *(float4*)qa = *(const float4*)&QsT[k * 68 + row0];
            *(float4*)kb = *(const float4*)&KsT[k * 68 + (tn << 2)];
#pragma unroll
            for (int i = 0; i < 4; i++)
#pragma unroll
                for (int j = 0; j < 4; j++)
                    s[i][j] = fmaf(qa[i], kb[j], s[i][j]);
        }

        float rmax[4];
#pragma unroll
        for (int i = 0; i < 4; i++) {
            int qi = m0 + row0 + i;
            rmax[i] = -1e30f;
#pragma unroll
            for (int j = 0; j < 4; j++) {
                int kj = n0 + (tn << 2) + j;
                float sv = (kj <= qi) ? s[i][j] * SCALE : -1e30f;
                s[i][j] = sv;
                rmax[i] = fmaxf(rmax[i], sv);
            }
        }
#pragma unroll
        for (int ofs = 8; ofs; ofs >>= 1)
#pragma unroll
            for (int i = 0; i < 4; i++)
                rmax[i] = fmaxf(rmax[i], __shfl_xor_sync(0xffffffffu, rmax[i], ofs));

        float mnew[4], alpha[4], rsum[4];
#pragma unroll
        for (int i = 0; i < 4; i++) {
            mnew[i]  = fmaxf(m_i[i], rmax[i]);
            alpha[i] = __expf(m_i[i] - mnew[i]);
            float rs = 0.f;
#pragma unroll
            for (int j = 0; j < 4; j++) {
                float p = __expf(s[i][j] - mnew[i]);
                Ps[(row0 + i) * 68 + (tn << 2) + j] = p;
                rs += p;
            }
            rsum[i] = rs;
        }
#pragma unroll
        for (int ofs = 8; ofs; ofs >>= 1)
#pragma unroll
            for (int i = 0; i < 4; i++)
                rsum[i] += __shfl_xor_sync(0xffffffffu, rsum[i], ofs);
#pragma unroll
        for (int i = 0; i < 4; i++) {
            l_i[i] = l_i[i] * alpha[i] + rsum[i];
            m_i[i] = mnew[i];
#pragma unroll
            for (int c = 0; c < 8; c++) acc[i][c] *= alpha[i];
        }
        __syncthreads();

#pragma unroll 2
        for (int j = 0; j < 64; j++) {
            float p0 = Ps[(row0 + 0) * 68 + j];
            float p1 = Ps[(row0 + 1) * 68 + j];
            float p2 = Ps[(row0 + 2) * 68 + j];
            float p3 = Ps[(row0 + 3) * 68 + j];
            float v[8];
            *(float4*)&v[0] = *(const float4*)&Vs[j * 132 + (tn << 3)];
            *(float4*)&v[4] = *(const float4*)&Vs[j * 132 + (tn << 3) + 4];
#pragma unroll
            for (int c = 0; c < 8; c++) {
                acc[0][c] = fmaf(p0, v[c], acc[0][c]);
                acc[1][c] = fmaf(p1, v[c], acc[1][c]);
                acc[2][c] = fmaf(p2, v[c], acc[2][c]);
                acc[3][c] = fmaf(p3, v[c], acc[3][c]);
            }
        }
        __syncthreads();
    }

#pragma unroll
    for (int i = 0; i < 4; i++) {
        float inv = 1.0f / l_i[i];
        float* cdst = ctx + (size_t)(b * T_ + m0 + row0 + i) * QCOLS + h * 128 + (tn << 3);
        *(float4*)cdst       = make_float4(rna_tf32(acc[i][0] * inv), rna_tf32(acc[i][1] * inv),
                                           rna_tf32(acc[i][2] * inv), rna_tf32(acc[i][3] * inv));
        *(float4*)(cdst + 4) = make_float4(rna_tf32(acc[i][4] * inv), rna_tf32(acc[i][5] * inv),
                                           rna_tf32(acc[i][6] * inv), rna_tf32(acc[i][7] * inv));
    }
}

// ---------------------------------------------------------------------------
// Host
// ---------------------------------------------------------------------------
extern "C" void kernel_launch(void* const* d_in, const int* in_sizes, int n_in,
                              void* d_out, int out_size) {
    const float* x    = (const float*)d_in[0];
    const float* Wq   = (const float*)d_in[1];
    const float* Wk   = (const float*)d_in[2];
    const float* Wv   = (const float*)d_in[3];
    const float* Wout = (const float*)d_in[4];
    float* out = (float*)d_out;

    float *xr, *Wqr, *Wkr, *Wvr, *Wor, *Qb, *Kb, *Vb, *Cb;
    cudaGetSymbolAddress((void**)&xr,  g_xr);
    cudaGetSymbolAddress((void**)&Wqr, g_Wq);
    cudaGetSymbolAddress((void**)&Wkr, g_Wk);
    cudaGetSymbolAddress((void**)&Wvr, g_Wv);
    cudaGetSymbolAddress((void**)&Wor, g_Wo);
    cudaGetSymbolAddress((void**)&Qb,  g_Q);
    cudaGetSymbolAddress((void**)&Kb,  g_K);
    cudaGetSymbolAddress((void**)&Vb,  g_V);
    cudaGetSymbolAddress((void**)&Cb,  g_ctx);

    cudaFuncSetAttribute(gemm_mma, cudaFuncAttributeMaxDynamicSharedMemorySize, GSMEM_BYTES);
    const size_t fa_smem = (size_t)FA_SMEM_FLOATS * sizeof(float);
    cudaFuncSetAttribute(flash_kernel, cudaFuncAttributeMaxDynamicSharedMemorySize, (int)fa_smem);

    // Operand prep (tf32-RN rounding copies)
    prep_round<<<(ROWS * E_ / 4 + 255) / 256, 256>>>(x,    xr,  ROWS * E_ / 4);
    prep_round<<<(E_ * QCOLS / 4 + 255) / 256, 256>>>(Wq,  Wqr, E_ * QCOLS / 4);
    prep_round<<<(E_ * KCOLS / 4 + 255) / 256, 256>>>(Wk,  Wkr, E_ * KCOLS / 4);
    prep_round<<<(E_ * KCOLS / 4 + 255) / 256, 256>>>(Wv,  Wvr, E_ * KCOLS / 4);
    prep_round<<<(QCOLS * E_ / 4 + 255) / 256, 256>>>(Wout, Wor, QCOLS * E_ / 4);

    // Projections (tf32 mma.sync)
    gemm_mma<<<dim3(QCOLS/GBN, ROWS/GBM), 256, GSMEM_BYTES>>>(xr, Wqr, Qb, ROWS, QCOLS, E_);
    gemm_mma<<<dim3(KCOLS/GBN, ROWS/GBM), 256, GSMEM_BYTES>>>(xr, Wkr, Kb, ROWS, KCOLS, E_);
    gemm_mma<<<dim3(KCOLS/GBN, ROWS/GBM), 256, GSMEM_BYTES>>>(xr, Wvr, Vb, ROWS, KCOLS, E_);

    // RoPE
    {
        int totq = ROWS * H_ * 64;
        rope_kernel<<<(totq + 255) / 256, 256>>>(Qb, H_, totq);
        int totk = ROWS * HKV_ * 64;
        rope_kernel<<<(totk + 255) / 256, 256>>>(Kb, HKV_, totk);
    }

    // Attention
    flash_kernel<<<dim3(T_ / 64, H_, B_), 256, fa_smem>>>(Qb, Kb, Vb, Cb);

    // Output projection
    gemm_mma<<<dim3(E_/GBN, ROWS/GBM), 256, GSMEM_BYTES>>>(Cb, Wor, out, ROWS, E_, QCOLS);
}

// round 4
// speedup vs baseline: 3.9999x; 2.2198x over previous
#include <cuda_runtime.h>
#include <cuda_bf16.h>
#include <math.h>
#include <stdint.h>

// Problem constants
#define B_   2
#define T_   2048
#define E_   2048
#define H_   16
#define HKV_ 4
#define D_   128
#define ROWS (B_ * T_)          // 4096
#define QCOLS (H_ * D_)         // 2048
#define KCOLS (HKV_ * D_)       // 512

// ---------------------------------------------------------------------------
// Scratch (allocation-free: device globals)
// ---------------------------------------------------------------------------
__device__ __align__(1024) float g_xr [(size_t)ROWS * E_];      // tf32-rounded x
__device__ __align__(1024) float g_Wq [(size_t)E_ * QCOLS];     // rounded weights
__device__ __align__(1024) float g_Wk [(size_t)E_ * KCOLS];
__device__ __align__(1024) float g_Wv [(size_t)E_ * KCOLS];
__device__ __align__(1024) float g_Wo [(size_t)QCOLS * E_];
__device__ __align__(1024) float g_Q  [(size_t)ROWS * QCOLS];
__device__ __align__(1024) float g_K  [(size_t)ROWS * KCOLS];
__device__ __align__(1024) float g_V  [(size_t)ROWS * KCOLS];
__device__ __align__(1024) float g_ctx[(size_t)ROWS * QCOLS];

// ---------------------------------------------------------------------------
// Helpers
// ---------------------------------------------------------------------------
__device__ __forceinline__ float rna_tf32(float x) {
    uint32_t y;
    asm("cvt.rna.tf32.f32 %0, %1;" : "=r"(y) : "f"(x));
    return __uint_as_float(y);
}
__device__ __forceinline__ uint32_t smem_u32(const void* p) {
    uint32_t a;
    asm("{ .reg .u64 t; cvta.to.shared.u64 t, %1; cvt.u32.u64 %0, t; }" : "=r"(a) : "l"(p));
    return a;
}
__device__ __forceinline__ void cp_async16(uint32_t saddr, const void* gptr) {
    asm volatile("cp.async.cg.shared.global [%0], [%1], 16;" :: "r"(saddr), "l"(gptr));
}
#define CP_COMMIT() asm volatile("cp.async.commit_group;" ::: "memory")
#define CP_WAIT(n)  asm volatile("cp.async.wait_group %0;" :: "n"(n) : "memory")

__device__ __forceinline__ void mma_tf32(float* c, const uint32_t* a, const uint32_t* b) {
    asm volatile(
        "mma.sync.aligned.m16n8k8.row.col.f32.tf32.tf32.f32 "
        "{%0,%1,%2,%3}, {%4,%5,%6,%7}, {%8,%9}, {%0,%1,%2,%3};"
        : "+f"(c[0]), "+f"(c[1]), "+f"(c[2]), "+f"(c[3])
        : "r"(a[0]), "r"(a[1]), "r"(a[2]), "r"(a[3]), "r"(b[0]), "r"(b[1]));
}

// ---------------------------------------------------------------------------
// TF32 mma.sync GEMM: C[M,N] = A[M,K] @ B[K,N], row-major, tf32-rounded in.
// Tile 128x128x32, 3-stage cp.async pipeline, 256 threads (8 warps, 4x2).
// ---------------------------------------------------------------------------
#define GBM 128
#define GBN 128
#define GBK 32
#define GAST 36
#define GBST 136
#define GSTAGES 3
#define GA_FLOATS (GBM * GAST)
#define GB_FLOATS (GBK * GBST)
#define GSTAGE_FLOATS (GA_FLOATS + GB_FLOATS)
#define GSMEM_BYTES (GSTAGES * GSTAGE_FLOATS * 4)

__global__ __launch_bounds__(256) void gemm_mma(const float* __restrict__ A,
                                                const float* __restrict__ Bw,
                                                float* __restrict__ C,
                                                int M, int N, int K, int round_out) {
    extern __shared__ __align__(16) float smem[];
    const int tid = threadIdx.x;
    const int wid = tid >> 5, lane = tid & 31;
    const int warpM = wid & 3, warpN = wid >> 2;
    const int m0 = blockIdx.y * GBM, n0 = blockIdx.x * GBN;
    const int nch = K / GBK;
    const int lr = lane >> 2, lc = lane & 3;

    float acc[2][8][4];
#pragma unroll
    for (int i = 0; i < 2; i++)
#pragma unroll
        for (int j = 0; j < 8; j++)
#pragma unroll
            for (int q = 0; q < 4; q++) acc[i][j][q] = 0.f;

    auto load_chunk = [&](int c, int s) {
        float* As = smem + s * GSTAGE_FLOATS;
        float* Bs = As + GA_FLOATS;
        const uint32_t as_base = smem_u32(As);
        const uint32_t bs_base = smem_u32(Bs);
#pragma unroll
        for (int i = 0; i < 4; i++) {
            int ci = tid + i * 256;
            int row = ci >> 3, ch = ci & 7;
            cp_async16(as_base + (row * GAST + ch * 4) * 4,
                       A + (size_t)(m0 + row) * K + c * GBK + ch * 4);
        }
#pragma unroll
        for (int i = 0; i < 4; i++) {
            int ci = tid + i * 256;
            int row = ci >> 5, ch = ci & 31;
            cp_async16(bs_base + (row * GBST + ch * 4) * 4,
                       Bw + (size_t)(c * GBK + row) * N + n0 + ch * 4);
        }
    };

#pragma unroll
    for (int s = 0; s < GSTAGES - 1; s++) { load_chunk(s, s); CP_COMMIT(); }

    for (int c = 0; c < nch; c++) {
        CP_WAIT(GSTAGES - 2);
        __syncthreads();

        int pc = c + GSTAGES - 1;
        if (pc < nch) load_chunk(pc, pc % GSTAGES);
        CP_COMMIT();

        const float* As = smem + (c % GSTAGES) * GSTAGE_FLOATS;
        const float* Bs = As + GA_FLOATS;
        const uint32_t* Asu = (const uint32_t*)As;
        const uint32_t* Bsu = (const uint32_t*)Bs;

#pragma unroll
        for (int kk = 0; kk < 4; kk++) {
            uint32_t afr[2][4], bfr[8][2];
#pragma unroll
            for (int mt = 0; mt < 2; mt++) {
                int row = warpM * 32 + mt * 16 + lr;
                int col = kk * 8 + lc;
                afr[mt][0] = Asu[row * GAST + col];
                afr[mt][1] = Asu[(row + 8) * GAST + col];
                afr[mt][2] = Asu[row * GAST + col + 4];
                afr[mt][3] = Asu[(row + 8) * GAST + col + 4];
            }
#pragma unroll
            for (int nt = 0; nt < 8; nt++) {
                int n = warpN * 64 + nt * 8 + lr;
                int k = kk * 8 + lc;
                bfr[nt][0] = Bsu[k * GBST + n];
                bfr[nt][1] = Bsu[(k + 4) * GBST + n];
            }
#pragma unroll
            for (int mt = 0; mt < 2; mt++)
#pragma unroll
                for (int nt = 0; nt < 8; nt++)
                    mma_tf32(acc[mt][nt], afr[mt], bfr[nt]);
        }
        __syncthreads();
    }

#pragma unroll
    for (int mt = 0; mt < 2; mt++) {
        int rbase = m0 + warpM * 32 + mt * 16 + lr;
#pragma unroll
        for (int nt = 0; nt < 8; nt++) {
            int cbase = n0 + warpN * 64 + nt * 8 + lc * 2;
            float4 vals = make_float4(acc[mt][nt][0], acc[mt][nt][1],
                                      acc[mt][nt][2], acc[mt][nt][3]);
            if (round_out) {
                vals.x = rna_tf32(vals.x); vals.y = rna_tf32(vals.y);
                vals.z = rna_tf32(vals.z); vals.w = rna_tf32(vals.w);
            }
            *(float2*)(C + (size_t)rbase * N + cbase)       = make_float2(vals.x, vals.y);
            *(float2*)(C + (size_t)(rbase + 8) * N + cbase) = make_float2(vals.z, vals.w);
        }
    }
}

// ---------------------------------------------------------------------------
// prep: tf32-RN rounding copy.
// ---------------------------------------------------------------------------
__global__ void prep_round(const float* __restrict__ in, float* __restrict__ out, int n4) {
    int i = blockIdx.x * blockDim.x + threadIdx.x;
    if (i >= n4) return;
    float4 v = ((const float4*)in)[i];
    v.x = rna_tf32(v.x); v.y = rna_tf32(v.y); v.z = rna_tf32(v.z); v.w = rna_tf32(v.w);
    ((float4*)out)[i] = v;
}

// ---------------------------------------------------------------------------
// RoPE in-place, applies extra scale, rounds output to tf32-RN.
// ---------------------------------------------------------------------------
__global__ void rope_kernel(float* __restrict__ X, int nheads, int total, float scale) {
    int idx = blockIdx.x * blockDim.x + threadIdx.x;
    if (idx >= total) return;
    const int pairs_per_row = nheads * 64;
    int row = idx / pairs_per_row;
    int p   = idx - row * pairs_per_row;
    int h = p >> 6;
    int i = p & 63;
    int t = row & (T_ - 1);

    double w = pow(10000.0, -(double)i / 64.0);
    double ang = (double)t * w;
    double ds, dc;
    sincos(ang, &ds, &dc);
    float s = (float)ds, c = (float)dc;

    float* base = X + (size_t)row * (nheads * 128) + h * 128 + 2 * i;
    float re = base[0], im = base[1];
    base[0] = rna_tf32((re * c - im * s) * scale);
    base[1] = rna_tf32((re * s + im * c) * scale);
}

// ---------------------------------------------------------------------------
// Causal flash attention with tf32 mma.sync.
// BLOCK_M=128 (8 warps x 16 rows), BLOCK_N=64, D=128.
// Q pre-scaled by 1/sqrt(D) and tf32-rounded. K, V tf32-rounded.
// K/V double-buffered via cp.async; per-warp P scratch in smem.
// ---------------------------------------------------------------------------
#define FBM 128
#define FBN 64
#define KST 132   // Ks row stride (floats); 132 % 32 == 4 -> conflict-free B frags
#define VST 136   // Vs row stride; 136 % 32 == 8 -> conflict-free B frags
#define PST 68    // per-warp P stride; 68 % 32 == 4 -> conflict-free A frags
#define KS_FLOATS (2 * 64 * KST)
#define VS_FLOATS (2 * 64 * VST)
#define PS_FLOATS (8 * 16 * PST)
#define FA_SMEM_BYTES ((KS_FLOATS + VS_FLOATS + PS_FLOATS) * 4)   // 172032

__global__ __launch_bounds__(256, 1) void flash_mma(const float* __restrict__ Q,
                                                    const float* __restrict__ Km,
                                                    const float* __restrict__ Vm,
                                                    float* __restrict__ ctx) {
    extern __shared__ __align__(16) float sm[];
    float* KsB = sm;
    float* VsB = sm + KS_FLOATS;
    float* PsB = VsB + VS_FLOATS;

    const int tid = threadIdx.x;
    const int wid = tid >> 5, lane = tid & 31;
    const int lr = lane >> 2, lc = lane & 3;
    const int m0 = (int)(gridDim.x - 1 - blockIdx.x) * FBM;   // heavy blocks first
    const int h = blockIdx.y, b = blockIdx.z;
    const int kvh = h >> 2;

    float* Psw = PsB + wid * 16 * PST;
    uint32_t* Psu = (uint32_t*)Psw;

    // ---- Load Q tile for this warp into A-fragments (via Psw staging) ----
    uint32_t qa[16][4];
    {
        const float* qsrc = Q + (size_t)(b * T_ + m0 + wid * 16) * QCOLS + h * 128;
#pragma unroll
        for (int hh = 0; hh < 2; hh++) {
#pragma unroll
            for (int i = 0; i < 8; i++) {
                int task = lane + i * 32;           // 256 float4 tasks
                int row = task >> 4, c4 = task & 15;
                float4 v = *(const float4*)(qsrc + (size_t)row * QCOLS + hh * 64 + c4 * 4);
                *(float4*)&Psw[row * PST + c4 * 4] = v;
            }
            __syncwarp();
#pragma unroll
            for (int k8 = 0; k8 < 8; k8++) {
                int kk = hh * 8 + k8;
                qa[kk][0] = Psu[lr * PST + k8 * 8 + lc];
                qa[kk][1] = Psu[(lr + 8) * PST + k8 * 8 + lc];
                qa[kk][2] = Psu[lr * PST + k8 * 8 + lc + 4];
                qa[kk][3] = Psu[(lr + 8) * PST + k8 * 8 + lc + 4];
            }
            __syncwarp();
        }
    }

    float oacc[16][4];
#pragma unroll
    for (int i = 0; i < 16; i++)
#pragma unroll
        for (int q = 0; q < 4; q++) oacc[i][q] = 0.f;
    float m_i[2] = {-1e30f, -1e30f};
    float l_i[2] = {0.f, 0.f};

    const int ntiles = m0 / 64 + 2;

    auto load_kv = [&](int t, int stg) {
        const float* kb = Km + (size_t)(b * T_ + t * 64) * KCOLS + kvh * 128;
        const float* vb = Vm + (size_t)(b * T_ + t * 64) * KCOLS + kvh * 128;
        uint32_t ka = smem_u32(KsB + stg * 64 * KST);
        uint32_t va = smem_u32(VsB + stg * 64 * VST);
#pragma unroll
        for (int i = 0; i < 8; i++) {
            int task = tid + i * 256;       // 2048 float4 tasks
            int row = task >> 5, ch = task & 31;
            cp_async16(ka + (row * KST + ch * 4) * 4, kb + (size_t)row * KCOLS + ch * 4);
        }
#pragma unroll
        for (int i = 0; i < 8; i++) {
            int task = tid + i * 256;
            int row = task >> 5, ch = task & 31;
            cp_async16(va + (row * VST + ch * 4) * 4, vb + (size_t)row * KCOLS + ch * 4);
        }
    };

    load_kv(0, 0);
    CP_COMMIT();

    for (int t = 0; t < ntiles; t++) {
        if (t + 1 < ntiles) { load_kv(t + 1, (t + 1) & 1); CP_COMMIT(); CP_WAIT(1); }
        else                { CP_WAIT(0); }
        __syncthreads();

        const uint32_t* Ksu = (const uint32_t*)(KsB + (t & 1) * 64 * KST);
        const uint32_t* Vsu = (const uint32_t*)(VsB + (t & 1) * 64 * VST);

        // ---- S = Q K^T ----
        float sacc[8][4];
#pragma unroll
        for (int nt = 0; nt < 8; nt++)
#pragma unroll
            for (int q = 0; q < 4; q++) sacc[nt][q] = 0.f;

#pragma unroll
        for (int kk = 0; kk < 16; kk++) {
            uint32_t bfr[8][2];
#pragma unroll
            for (int nt = 0; nt < 8; nt++) {
                bfr[nt][0] = Ksu[(nt * 8 + lr) * KST + kk * 8 + lc];
                bfr[nt][1] = Ksu[(nt * 8 + lr) * KST + kk * 8 + lc + 4];
            }
#pragma unroll
            for (int nt = 0; nt < 8; nt++)
                mma_tf32(sacc[nt], qa[kk], bfr[nt]);
        }

        // ---- causal mask ----
        const int row0g = m0 + wid * 16 + lr;
        const int row1g = row0g + 8;
        if (t * 64 + 63 > m0 + wid * 16) {
#pragma unroll
            for (int nt = 0; nt < 8; nt++) {
                int colg = t * 64 + nt * 8 + 2 * lc;
                if (colg     > row0g) sacc[nt][0] = -1e30f;
                if (colg + 1 > row0g) sacc[nt][1] = -1e30f;
                if (colg     > row1g) sacc[nt][2] = -1e30f;
                if (colg + 1 > row1g) sacc[nt][3] = -1e30f;
            }
        }

        // ---- online softmax ----
        float rmax0 = -1e30f, rmax1 = -1e30f;
#pragma unroll
        for (int nt = 0; nt < 8; nt++) {
            rmax0 = fmaxf(rmax0, fmaxf(sacc[nt][0], sacc[nt][1]));
            rmax1 = fmaxf(rmax1, fmaxf(sacc[nt][2], sacc[nt][3]));
        }
        rmax0 = fmaxf(rmax0, __shfl_xor_sync(0xffffffffu, rmax0, 1));
        rmax0 = fmaxf(rmax0, __shfl_xor_sync(0xffffffffu, rmax0, 2));
        rmax1 = fmaxf(rmax1, __shfl_xor_sync(0xffffffffu, rmax1, 1));
        rmax1 = fmaxf(rmax1, __shfl_xor_sync(0xffffffffu, rmax1, 2));

        float mnew0 = fmaxf(m_i[0], rmax0);
        float mnew1 = fmaxf(m_i[1], rmax1);
        float alpha0 = __expf(m_i[0] - mnew0);
        float alpha1 = __expf(m_i[1] - mnew1);

        float rsum0 = 0.f, rsum1 = 0.f;
#pragma unroll
        for (int nt = 0; nt < 8; nt++) {
            float p0 = rna_tf32(__expf(sacc[nt][0] - mnew0));
            float p1 = rna_tf32(__expf(sacc[nt][1] - mnew0));
            float p2 = rna_tf32(__expf(sacc[nt][2] - mnew1));
            float p3 = rna_tf32(__expf(sacc[nt][3] - mnew1));
            rsum0 += p0 + p1;
            rsum1 += p2 + p3;
            *(float2*)&Psw[lr * PST + nt * 8 + 2 * lc]       = make_float2(p0, p1);
            *(float2*)&Psw[(lr + 8) * PST + nt * 8 + 2 * lc] = make_float2(p2, p3);
        }
        rsum0 += __shfl_xor_sync(0xffffffffu, rsum0, 1);
        rsum0 += __shfl_xor_sync(0xffffffffu, rsum0, 2);
        rsum1 += __shfl_xor_sync(0xffffffffu, rsum1, 1);
        rsum1 += __shfl_xor_sync(0xffffffffu, rsum1, 2);

        l_i[0] = l_i[0] * alpha0 + rsum0;
        l_i[1] = l_i[1] * alpha1 + rsum1;
        m_i[0] = mnew0;
        m_i[1] = mnew1;
#pragma unroll
        for (int nt = 0; nt < 16; nt++) {
            oacc[nt][0] *= alpha0; oacc[nt][1] *= alpha0;
            oacc[nt][2] *= alpha1; oacc[nt][3] *= alpha1;
        }
        __syncwarp();

        // ---- O += P V ----
#pragma unroll
        for (int kk = 0; kk < 8; kk++) {
            uint32_t pa[4];
            pa[0] = Psu[lr * PST + kk * 8 + lc];
            pa[1] = Psu[(lr + 8) * PST + kk * 8 + lc];
            pa[2] = Psu[lr * PST + kk * 8 + lc + 4];
            pa[3] = Psu[(lr + 8) * PST + kk * 8 + lc + 4];
#pragma unroll
            for (int nt = 0; nt < 16; nt++) {
                uint32_t bfr[2];
                bfr[0] = Vsu[(kk * 8 + lc) * VST + nt * 8 + lr];
                bfr[1] = Vsu[(kk * 8 + lc + 4) * VST + nt * 8 + lr];
                mma_tf32(oacc[nt], pa, bfr);
            }
        }
        __syncwarp();
        __syncthreads();
    }

    // ---- epilogue ----
    float inv0 = 1.0f / l_i[0];
    float inv1 = 1.0f / l_i[1];
    const int row0g = m0 + wid * 16 + lr;
    float* c0 = ctx + (size_t)(b * T_ + row0g) * QCOLS + h * 128;
    float* c1 = ctx + (size_t)(b * T_ + row0g + 8) * QCOLS + h * 128;
#pragma unroll
    for (int nt = 0; nt < 16; nt++) {
        int col = nt * 8 + 2 * lc;
        *(float2*)(c0 + col) = make_float2(rna_tf32(oacc[nt][0] * inv0),
                                           rna_tf32(oacc[nt][1] * inv0));
        *(float2*)(c1 + col) = make_float2(rna_tf32(oacc[nt][2] * inv1),
                                           rna_tf32(oacc[nt][3] * inv1));
    }
}

// ---------------------------------------------------------------------------
// Host
// ---------------------------------------------------------------------------
extern "C" void kernel_launch(void* const* d_in, const int* in_sizes, int n_in,
                              void* d_out, int out_size) {
    const float* x    = (const float*)d_in[0];
    const float* Wq   = (const float*)d_in[1];
    const float* Wk   = (const float*)d_in[2];
    const float* Wv   = (const float*)d_in[3];
    const float* Wout = (const float*)d_in[4];
    float* out = (float*)d_out;

    float *xr, *Wqr, *Wkr, *Wvr, *Wor, *Qb, *Kb, *Vb, *Cb;
    cudaGetSymbolAddress((void**)&xr,  g_xr);
    cudaGetSymbolAddress((void**)&Wqr, g_Wq);
    cudaGetSymbolAddress((void**)&Wkr, g_Wk);
    cudaGetSymbolAddress((void**)&Wvr, g_Wv);
    cudaGetSymbolAddress((void**)&Wor, g_Wo);
    cudaGetSymbolAddress((void**)&Qb,  g_Q);
    cudaGetSymbolAddress((void**)&Kb,  g_K);
    cudaGetSymbolAddress((void**)&Vb,  g_V);
    cudaGetSymbolAddress((void**)&Cb,  g_ctx);

    cudaFuncSetAttribute(gemm_mma, cudaFuncAttributeMaxDynamicSharedMemorySize, GSMEM_BYTES);
    cudaFuncSetAttribute(flash_mma, cudaFuncAttributeMaxDynamicSharedMemorySize, FA_SMEM_BYTES);

    // Operand prep (tf32-RN rounding copies)
    prep_round<<<(ROWS * E_ / 4 + 255) / 256, 256>>>(x,    xr,  ROWS * E_ / 4);
    prep_round<<<(E_ * QCOLS / 4 + 255) / 256, 256>>>(Wq,  Wqr, E_ * QCOLS / 4);
    prep_round<<<(E_ * KCOLS / 4 + 255) / 256, 256>>>(Wk,  Wkr, E_ * KCOLS / 4);
    prep_round<<<(E_ * KCOLS / 4 + 255) / 256, 256>>>(Wv,  Wvr, E_ * KCOLS / 4);
    prep_round<<<(QCOLS * E_ / 4 + 255) / 256, 256>>>(Wout, Wor, QCOLS * E_ / 4);

    // Projections (tf32 mma.sync). V output rounded (feeds PV mma directly).
    gemm_mma<<<dim3(QCOLS/GBN, ROWS/GBM), 256, GSMEM_BYTES>>>(xr, Wqr, Qb, ROWS, QCOLS, E_, 0);
    gemm_mma<<<dim3(KCOLS/GBN, ROWS/GBM), 256, GSMEM_BYTES>>>(xr, Wkr, Kb, ROWS, KCOLS, E_, 0);
    gemm_mma<<<dim3(KCOLS/GBN, ROWS/GBM), 256, GSMEM_BYTES>>>(xr, Wvr, Vb, ROWS, KCOLS, E_, 1);

    // RoPE: Q gets 1/sqrt(D) folded in; both outputs tf32-rounded.
    {
        int totq = ROWS * H_ * 64;
        rope_kernel<<<(totq + 255) / 256, 256>>>(Qb, H_, totq, 0.08838834764831845f);
        int totk = ROWS * HKV_ * 64;
        rope_kernel<<<(totk + 255) / 256, 256>>>(Kb, HKV_, totk, 1.0f);
    }

    // Attention (tf32 mma.sync flash)
    flash_mma<<<dim3(T_ / FBM, H_, B_), 256, FA_SMEM_BYTES>>>(Qb, Kb, Vb, Cb);

    // Output projection (no rounding on final result)
    gemm_mma<<<dim3(E_/GBN, ROWS/GBM), 256, GSMEM_BYTES>>>(Cb, Wor, out, ROWS, E_, QCOLS, 0);
}

// round 5
// speedup vs baseline: 4.2252x; 1.0563x over previous
#include <cuda_runtime.h>
#include <cuda_bf16.h>
#include <math.h>
#include <stdint.h>

// Problem constants
#define B_   2
#define T_   2048
#define E_   2048
#define H_   16
#define HKV_ 4
#define D_   128
#define ROWS (B_ * T_)          // 4096
#define QCOLS (H_ * D_)         // 2048
#define KCOLS (HKV_ * D_)       // 512

// ---------------------------------------------------------------------------
// Scratch (allocation-free: device globals)
// ---------------------------------------------------------------------------
__device__ __align__(1024) float g_xr [(size_t)ROWS * E_];
__device__ __align__(1024) float g_Wq [(size_t)E_ * QCOLS];
__device__ __align__(1024) float g_Wk [(size_t)E_ * KCOLS];
__device__ __align__(1024) float g_Wv [(size_t)E_ * KCOLS];
__device__ __align__(1024) float g_Wo [(size_t)QCOLS * E_];
__device__ __align__(1024) float g_Q  [(size_t)ROWS * QCOLS];
__device__ __align__(1024) float g_K  [(size_t)ROWS * KCOLS];
__device__ __align__(1024) float g_V  [(size_t)ROWS * KCOLS];
__device__ __align__(1024) float g_ctx[(size_t)ROWS * QCOLS];
__device__ __align__(1024) float g_rcos[T_ * 64];
__device__ __align__(1024) float g_rsin[T_ * 64];

// ---------------------------------------------------------------------------
// Helpers
// ---------------------------------------------------------------------------
__device__ __forceinline__ float rna_tf32(float x) {
    uint32_t y;
    asm("cvt.rna.tf32.f32 %0, %1;" : "=r"(y) : "f"(x));
    return __uint_as_float(y);
}
__device__ __forceinline__ uint32_t smem_u32(const void* p) {
    uint32_t a;
    asm("{ .reg .u64 t; cvta.to.shared.u64 t, %1; cvt.u32.u64 %0, t; }" : "=r"(a) : "l"(p));
    return a;
}
__device__ __forceinline__ void cp_async16(uint32_t saddr, const void* gptr) {
    asm volatile("cp.async.cg.shared.global [%0], [%1], 16;" :: "r"(saddr), "l"(gptr));
}
#define CP_COMMIT() asm volatile("cp.async.commit_group;" ::: "memory")
#define CP_WAIT(n)  asm volatile("cp.async.wait_group %0;" :: "n"(n) : "memory")

__device__ __forceinline__ void mma_tf32(float* c, const uint32_t* a, const uint32_t* b) {
    asm volatile(
        "mma.sync.aligned.m16n8k8.row.col.f32.tf32.tf32.f32 "
        "{%0,%1,%2,%3}, {%4,%5,%6,%7}, {%8,%9}, {%0,%1,%2,%3};"
        : "+f"(c[0]), "+f"(c[1]), "+f"(c[2]), "+f"(c[3])
        : "r"(a[0]), "r"(a[1]), "r"(a[2]), "r"(a[3]), "r"(b[0]), "r"(b[1]));
}

// ---------------------------------------------------------------------------
// Rope cos/sin table (double-precision source, fp32 table).
// ---------------------------------------------------------------------------
__global__ void rope_table(float* __restrict__ ct, float* __restrict__ st) {
    int idx = blockIdx.x * blockDim.x + threadIdx.x;
    if (idx >= T_ * 64) return;
    int t = idx >> 6, i = idx & 63;
    double w = pow(10000.0, -(double)i / 64.0);
    double ds, dc;
    sincos((double)t * w, &ds, &dc);
    ct[idx] = (float)dc;
    st[idx] = (float)ds;
}

// ---------------------------------------------------------------------------
// One-shot prep: tf32-RN rounding copy of all 5 operand tensors.
// ---------------------------------------------------------------------------
#define P_S0 (ROWS * E_ / 4)                 // 2097152
#define P_S1 (P_S0 + E_ * QCOLS / 4)         // +1048576
#define P_S2 (P_S1 + E_ * KCOLS / 4)         // +262144
#define P_S3 (P_S2 + E_ * KCOLS / 4)
#define P_S4 (P_S3 + QCOLS * E_ / 4)

__global__ void prep_all(const float* __restrict__ x,  const float* __restrict__ wq,
                         const float* __restrict__ wk, const float* __restrict__ wv,
                         const float* __restrict__ wo,
                         float* xr, float* wqr, float* wkr, float* wvr, float* wor) {
    int idx = blockIdx.x * blockDim.x + threadIdx.x;
    const float4* in; float4* out; int j;
    if      (idx < P_S0) { in = (const float4*)x;  out = (float4*)xr;  j = idx; }
    else if (idx < P_S1) { in = (const float4*)wq; out = (float4*)wqr; j = idx - P_S0; }
    else if (idx < P_S2) { in = (const float4*)wk; out = (float4*)wkr; j = idx - P_S1; }
    else if (idx < P_S3) { in = (const float4*)wv; out = (float4*)wvr; j = idx - P_S2; }
    else if (idx < P_S4) { in = (const float4*)wo; out = (float4*)wor; j = idx - P_S3; }
    else return;
    float4 v = in[j];
    v.x = rna_tf32(v.x); v.y = rna_tf32(v.y); v.z = rna_tf32(v.z); v.w = rna_tf32(v.w);
    out[j] = v;
}

// ---------------------------------------------------------------------------
// TF32 mma.sync GEMM with dual-output support and fused epilogues.
// C[M,N] = A[M,K] @ B[K,N]. Tile 128x128x32, 3-stage cp.async, 256 threads.
// Blocks bx < nblk1 compute matrix 1, the rest matrix 2 (same A, same N, K).
// mode: 0 = plain store, 1 = tf32-round store,
//       2 = rope + 1/sqrt(D) + round (Q), 3 = rope + round (K).
// ---------------------------------------------------------------------------
#define GBM 128
#define GBN 128
#define GBK 32
#define GAST 36
#define GBST 136
#define GSTAGES 3
#define GA_FLOATS (GBM * GAST)
#define GB_FLOATS (GBK * GBST)
#define GSTAGE_FLOATS (GA_FLOATS + GB_FLOATS)
#define GSMEM_BYTES (GSTAGES * GSTAGE_FLOATS * 4)

__global__ __launch_bounds__(256) void gemm_mma(
    const float* __restrict__ A,
    const float* __restrict__ B1, float* __restrict__ C1, int mode1, int nblk1,
    const float* __restrict__ B2, float* __restrict__ C2, int mode2,
    int N, int K,
    const float* __restrict__ ct, const float* __restrict__ st)
{
    extern __shared__ __align__(16) float smem[];
    const int tid = threadIdx.x;
    const int wid = tid >> 5, lane = tid & 31;
    const int warpM = wid & 3, warpN = wid >> 2;
    const int bx = blockIdx.x;

    const float* Bw; float* C; int mode, n0;
    if (bx < nblk1) { Bw = B1; C = C1; mode = mode1; n0 = bx * GBN; }
    else            { Bw = B2; C = C2; mode = mode2; n0 = (bx - nblk1) * GBN; }

    const int m0 = blockIdx.y * GBM;
    const int nch = K / GBK;
    const int lr = lane >> 2, lc = lane & 3;

    float acc[2][8][4];
#pragma unroll
    for (int i = 0; i < 2; i++)
#pragma unroll
        for (int j = 0; j < 8; j++)
#pragma unroll
            for (int q = 0; q < 4; q++) acc[i][j][q] = 0.f;

    auto load_chunk = [&](int c, int s) {
        float* As = smem + s * GSTAGE_FLOATS;
        float* Bs = As + GA_FLOATS;
        const uint32_t as_base = smem_u32(As);
        const uint32_t bs_base = smem_u32(Bs);
#pragma unroll
        for (int i = 0; i < 4; i++) {
            int ci = tid + i * 256;
            int row = ci >> 3, ch = ci & 7;
            cp_async16(as_base + (row * GAST + ch * 4) * 4,
                       A + (size_t)(m0 + row) * K + c * GBK + ch * 4);
        }
#pragma unroll
        for (int i = 0; i < 4; i++) {
            int ci = tid + i * 256;
            int row = ci >> 5, ch = ci & 31;
            cp_async16(bs_base + (row * GBST + ch * 4) * 4,
                       Bw + (size_t)(c * GBK + row) * N + n0 + ch * 4);
        }
    };

#pragma unroll
    for (int s = 0; s < GSTAGES - 1; s++) { load_chunk(s, s); CP_COMMIT(); }

    for (int c = 0; c < nch; c++) {
        CP_WAIT(GSTAGES - 2);
        __syncthreads();

        int pc = c + GSTAGES - 1;
        if (pc < nch) load_chunk(pc, pc % GSTAGES);
        CP_COMMIT();

        const float* As = smem + (c % GSTAGES) * GSTAGE_FLOATS;
        const float* Bs = As + GA_FLOATS;
        const uint32_t* Asu = (const uint32_t*)As;
        const uint32_t* Bsu = (const uint32_t*)Bs;

#pragma unroll
        for (int kk = 0; kk < 4; kk++) {
            uint32_t afr[2][4], bfr[8][2];
#pragma unroll
            for (int mt = 0; mt < 2; mt++) {
                int row = warpM * 32 + mt * 16 + lr;
                int col = kk * 8 + lc;
                afr[mt][0] = Asu[row * GAST + col];
                afr[mt][1] = Asu[(row + 8) * GAST + col];
                afr[mt][2] = Asu[row * GAST + col + 4];
                afr[mt][3] = Asu[(row + 8) * GAST + col + 4];
            }
#pragma unroll
            for (int nt = 0; nt < 8; nt++) {
                int n = warpN * 64 + nt * 8 + lr;
                int k = kk * 8 + lc;
                bfr[nt][0] = Bsu[k * GBST + n];
                bfr[nt][1] = Bsu[(k + 4) * GBST + n];
            }
#pragma unroll
            for (int mt = 0; mt < 2; mt++)
#pragma unroll
                for (int nt = 0; nt < 8; nt++)
                    mma_tf32(acc[mt][nt], afr[mt], bfr[nt]);
        }
        __syncthreads();
    }

    // ---- fused epilogue ----
#pragma unroll
    for (int mt = 0; mt < 2; mt++) {
        int rbase = m0 + warpM * 32 + mt * 16 + lr;
#pragma unroll
        for (int nt = 0; nt < 8; nt++) {
            int cbase = n0 + warpN * 64 + nt * 8 + lc * 2;
            float4 v = make_float4(acc[mt][nt][0], acc[mt][nt][1],
                                   acc[mt][nt][2], acc[mt][nt][3]);
            if (mode >= 2) {
                // (v.x, v.y) is the rope pair for row rbase; (v.z, v.w) for rbase+8.
                int i  = (cbase & 127) >> 1;
                int t0 = rbase & (T_ - 1);
                int t1 = (rbase + 8) & (T_ - 1);
                float c0 = ct[(t0 << 6) + i], s0 = st[(t0 << 6) + i];
                float c1 = ct[(t1 << 6) + i], s1 = st[(t1 << 6) + i];
                float scale = (mode == 2) ? 0.08838834764831845f : 1.0f;
                float x0 = (v.x * c0 - v.y * s0) * scale;
                float y0 = (v.x * s0 + v.y * c0) * scale;
                float x1 = (v.z * c1 - v.w * s1) * scale;
                float y1 = (v.z * s1 + v.w * c1) * scale;
                v = make_float4(rna_tf32(x0), rna_tf32(y0), rna_tf32(x1), rna_tf32(y1));
            } else if (mode == 1) {
                v.x = rna_tf32(v.x); v.y = rna_tf32(v.y);
                v.z = rna_tf32(v.z); v.w = rna_tf32(v.w);
            }
            *(float2*)(C + (size_t)rbase * N + cbase)       = make_float2(v.x, v.y);
            *(float2*)(C + (size_t)(rbase + 8) * N + cbase) = make_float2(v.z, v.w);
        }
    }
}

// ---------------------------------------------------------------------------
// Causal flash attention with tf32 mma.sync (unchanged from R4).
// ---------------------------------------------------------------------------
#define FBM 128
#define FBN 64
#define KST 132
#define VST 136
#define PST 68
#define KS_FLOATS (2 * 64 * KST)
#define VS_FLOATS (2 * 64 * VST)
#define PS_FLOATS (8 * 16 * PST)
#define FA_SMEM_BYTES ((KS_FLOATS + VS_FLOATS + PS_FLOATS) * 4)

__global__ __launch_bounds__(256, 1) void flash_mma(const float* __restrict__ Q,
                                                    const float* __restrict__ Km,
                                                    const float* __restrict__ Vm,
                                                    float* __restrict__ ctx) {
    extern __shared__ __align__(16) float sm[];
    float* KsB = sm;
    float* VsB = sm + KS_FLOATS;
    float* PsB = VsB + VS_FLOATS;

    const int tid = threadIdx.x;
    const int wid = tid >> 5, lane = tid & 31;
    const int lr = lane >> 2, lc = lane & 3;
    const int m0 = (int)(gridDim.x - 1 - blockIdx.x) * FBM;
    const int h = blockIdx.y, b = blockIdx.z;
    const int kvh = h >> 2;

    float* Psw = PsB + wid * 16 * PST;
    uint32_t* Psu = (uint32_t*)Psw;

    uint32_t qa[16][4];
    {
        const float* qsrc = Q + (size_t)(b * T_ + m0 + wid * 16) * QCOLS + h * 128;
#pragma unroll
        for (int hh = 0; hh < 2; hh++) {
#pragma unroll
            for (int i = 0; i < 8; i++) {
                int task = lane + i * 32;
                int row = task >> 4, c4 = task & 15;
                float4 v = *(const float4*)(qsrc + (size_t)row * QCOLS + hh * 64 + c4 * 4);
                *(float4*)&Psw[row * PST + c4 * 4] = v;
            }
            __syncwarp();
#pragma unroll
            for (int k8 = 0; k8 < 8; k8++) {
                int kk = hh * 8 + k8;
                qa[kk][0] = Psu[lr * PST + k8 * 8 + lc];
                qa[kk][1] = Psu[(lr + 8) * PST + k8 * 8 + lc];
                qa[kk][2] = Psu[lr * PST + k8 * 8 + lc + 4];
                qa[kk][3] = Psu[(lr + 8) * PST + k8 * 8 + lc + 4];
            }
            __syncwarp();
        }
    }

    float oacc[16][4];
#pragma unroll
    for (int i = 0; i < 16; i++)
#pragma unroll
        for (int q = 0; q < 4; q++) oacc[i][q] = 0.f;
    float m_i[2] = {-1e30f, -1e30f};
    float l_i[2] = {0.f, 0.f};

    const int ntiles = m0 / 64 + 2;

    auto load_kv = [&](int t, int stg) {
        const float* kb = Km + (size_t)(b * T_ + t * 64) * KCOLS + kvh * 128;
        const float* vb = Vm + (size_t)(b * T_ + t * 64) * KCOLS + kvh * 128;
        uint32_t ka = smem_u32(KsB + stg * 64 * KST);
        uint32_t va = smem_u32(VsB + stg * 64 * VST);
#pragma unroll
        for (int i = 0; i < 8; i++) {
            int task = tid + i * 256;
            int row = task >> 5, ch = task & 31;
            cp_async16(ka + (row * KST + ch * 4) * 4, kb + (size_t)row * KCOLS + ch * 4);
        }
#pragma unroll
        for (int i = 0; i < 8; i++) {
            int task = tid + i * 256;
            int row = task >> 5, ch = task & 31;
            cp_async16(va + (row * VST + ch * 4) * 4, vb + (size_t)row * KCOLS + ch * 4);
        }
    };

    load_kv(0, 0);
    CP_COMMIT();

    for (int t = 0; t < ntiles; t++) {
        if (t + 1 < ntiles) { load_kv(t + 1, (t + 1) & 1); CP_COMMIT(); CP_WAIT(1); }
        else                { CP_WAIT(0); }
        __syncthreads();

        const uint32_t* Ksu = (const uint32_t*)(KsB + (t & 1) * 64 * KST);
        const uint32_t* Vsu = (const uint32_t*)(VsB + (t & 1) * 64 * VST);

        float sacc[8][4];
#pragma unroll
        for (int nt = 0; nt < 8; nt++)
#pragma unroll
            for (int q = 0; q < 4; q++) sacc[nt][q] = 0.f;

#pragma unroll
        for (int kk = 0; kk < 16; kk++) {
            uint32_t bfr[8][2];
#pragma unroll
            for (int nt = 0; nt < 8; nt++) {
                bfr[nt][0] = Ksu[(nt * 8 + lr) * KST + kk * 8 + lc];
                bfr[nt][1] = Ksu[(nt * 8 + lr) * KST + kk * 8 + lc + 4];
            }
#pragma unroll
            for (int nt = 0; nt < 8; nt++)
                mma_tf32(sacc[nt], qa[kk], bfr[nt]);
        }

        const int row0g = m0 + wid * 16 + lr;
        const int row1g = row0g + 8;
        if (t * 64 + 63 > m0 + wid * 16) {
#pragma unroll
            for (int nt = 0; nt < 8; nt++) {
                int colg = t * 64 + nt * 8 + 2 * lc;
                if (colg     > row0g) sacc[nt][0] = -1e30f;
                if (colg + 1 > row0g) sacc[nt][1] = -1e30f;
                if (colg     > row1g) sacc[nt][2] = -1e30f;
                if (colg + 1 > row1g) sacc[nt][3] = -1e30f;
            }
        }

        float rmax0 = -1e30f, rmax1 = -1e30f;
#pragma unroll
        for (int nt = 0; nt < 8; nt++) {
            rmax0 = fmaxf(rmax0, fmaxf(sacc[nt][0], sacc[nt][1]));
            rmax1 = fmaxf(rmax1, fmaxf(sacc[nt][2], sacc[nt][3]));
        }
        rmax0 = fmaxf(rmax0, __shfl_xor_sync(0xffffffffu, rmax0, 1));
        rmax0 = fmaxf(rmax0, __shfl_xor_sync(0xffffffffu, rmax0, 2));
        rmax1 = fmaxf(rmax1, __shfl_xor_sync(0xffffffffu, rmax1, 1));
        rmax1 = fmaxf(rmax1, __shfl_xor_sync(0xffffffffu, rmax1, 2));

        float mnew0 = fmaxf(m_i[0], rmax0);
        float mnew1 = fmaxf(m_i[1], rmax1);
        float alpha0 = __expf(m_i[0] - mnew0);
        float alpha1 = __expf(m_i[1] - mnew1);

        float rsum0 = 0.f, rsum1 = 0.f;
#pragma unroll
        for (int nt = 0; nt < 8; nt++) {
            float p0 = rna_tf32(__expf(sacc[nt][0] - mnew0));
            float p1 = rna_tf32(__expf(sacc[nt][1] - mnew0));
            float p2 = rna_tf32(__expf(sacc[nt][2] - mnew1));
            float p3 = rna_tf32(__expf(sacc[nt][3] - mnew1));
            rsum0 += p0 + p1;
            rsum1 += p2 + p3;
            *(float2*)&Psw[lr * PST + nt * 8 + 2 * lc]       = make_float2(p0, p1);
            *(float2*)&Psw[(lr + 8) * PST + nt * 8 + 2 * lc] = make_float2(p2, p3);
        }
        rsum0 += __shfl_xor_sync(0xffffffffu, rsum0, 1);
        rsum0 += __shfl_xor_sync(0xffffffffu, rsum0, 2);
        rsum1 += __shfl_xor_sync(0xffffffffu, rsum1, 1);
        rsum1 += __shfl_xor_sync(0xffffffffu, rsum1, 2);

        l_i[0] = l_i[0] * alpha0 + rsum0;
        l_i[1] = l_i[1] * alpha1 + rsum1;
        m_i[0] = mnew0;
        m_i[1] = mnew1;
#pragma unroll
        for (int nt = 0; nt < 16; nt++) {
            oacc[nt][0] *= alpha0; oacc[nt][1] *= alpha0;
            oacc[nt][2] *= alpha1; oacc[nt][3] *= alpha1;
        }
        __syncwarp();

#pragma unroll
        for (int kk = 0; kk < 8; kk++) {
            uint32_t pa[4];
            pa[0] = Psu[lr * PST + kk * 8 + lc];
            pa[1] = Psu[(lr + 8) * PST + kk * 8 + lc];
            pa[2] = Psu[lr * PST + kk * 8 + lc + 4];
            pa[3] = Psu[(lr + 8) * PST + kk * 8 + lc + 4];
#pragma unroll
            for (int nt = 0; nt < 16; nt++) {
                uint32_t bfr[2];
                bfr[0] = Vsu[(kk * 8 + lc) * VST + nt * 8 + lr];
                bfr[1] = Vsu[(kk * 8 + lc + 4) * VST + nt * 8 + lr];
                mma_tf32(oacc[nt], pa, bfr);
            }
        }
        __syncwarp();
        __syncthreads();
    }

    float inv0 = 1.0f / l_i[0];
    float inv1 = 1.0f / l_i[1];
    const int row0g = m0 + wid * 16 + lr;
    float* c0 = ctx + (size_t)(b * T_ + row0g) * QCOLS + h * 128;
    float* c1 = ctx + (size_t)(b * T_ + row0g + 8) * QCOLS + h * 128;
#pragma unroll
    for (int nt = 0; nt < 16; nt++) {
        int col = nt * 8 + 2 * lc;
        *(float2*)(c0 + col) = make_float2(rna_tf32(oacc[nt][0] * inv0),
                                           rna_tf32(oacc[nt][1] * inv0));
        *(float2*)(c1 + col) = make_float2(rna_tf32(oacc[nt][2] * inv1),
                                           rna_tf32(oacc[nt][3] * inv1));
    }
}

// ---------------------------------------------------------------------------
// Host
// ---------------------------------------------------------------------------
extern "C" void kernel_launch(void* const* d_in, const int* in_sizes, int n_in,
                              void* d_out, int out_size) {
    const float* x    = (const float*)d_in[0];
    const float* Wq   = (const float*)d_in[1];
    const float* Wk   = (const float*)d_in[2];
    const float* Wv   = (const float*)d_in[3];
    const float* Wout = (const float*)d_in[4];
    float* out = (float*)d_out;

    float *xr, *Wqr, *Wkr, *Wvr, *Wor, *Qb, *Kb, *Vb, *Cb, *ctab, *stab;
    cudaGetSymbolAddress((void**)&xr,  g_xr);
    cudaGetSymbolAddress((void**)&Wqr, g_Wq);
    cudaGetSymbolAddress((void**)&Wkr, g_Wk);
    cudaGetSymbolAddress((void**)&Wvr, g_Wv);
    cudaGetSymbolAddress((void**)&Wor, g_Wo);
    cudaGetSymbolAddress((void**)&Qb,  g_Q);
    cudaGetSymbolAddress((void**)&Kb,  g_K);
    cudaGetSymbolAddress((void**)&Vb,  g_V);
    cudaGetSymbolAddress((void**)&Cb,  g_ctx);
    cudaGetSymbolAddress((void**)&ctab, g_rcos);
    cudaGetSymbolAddress((void**)&stab, g_rsin);

    cudaFuncSetAttribute(gemm_mma, cudaFuncAttributeMaxDynamicSharedMemorySize, GSMEM_BYTES);
    cudaFuncSetAttribute(flash_mma, cudaFuncAttributeMaxDynamicSharedMemorySize, FA_SMEM_BYTES);

    // 1) prep: round all operands to tf32-RN (one launch)
    prep_all<<<(P_S4 + 255) / 256, 256>>>(x, Wq, Wk, Wv, Wout, xr, Wqr, Wkr, Wvr, Wor);

    // 2) rope table
    rope_table<<<(T_ * 64 + 255) / 256, 256>>>(ctab, stab);

    // 3) Q projection with fused rope + 1/sqrt(D) + round (mode 2)
    gemm_mma<<<dim3(QCOLS / GBN, ROWS / GBM), 256, GSMEM_BYTES>>>(
        xr, Wqr, Qb, 2, QCOLS / GBN, Wqr, Qb, 2, QCOLS, E_, ctab, stab);

    // 4) K (rope, mode 3) + V (round, mode 1) fused in one launch
    gemm_mma<<<dim3(2 * KCOLS / GBN, ROWS / GBM), 256, GSMEM_BYTES>>>(
        xr, Wkr, Kb, 3, KCOLS / GBN, Wvr, Vb, 1, KCOLS, E_, ctab, stab);

    // 5) attention
    flash_mma<<<dim3(T_ / FBM, H_, B_), 256, FA_SMEM_BYTES>>>(Qb, Kb, Vb, Cb);

    // 6) output projection (plain store)
    gemm_mma<<<dim3(E_ / GBN, ROWS / GBM), 256, GSMEM_BYTES>>>(
        Cb, Wor, out, 0, E_ / GBN, Wor, out, 0, E_, QCOLS, ctab, stab);
}

// round 6
// speedup vs baseline: 4.3124x; 1.0206x over previous
#include <cuda_runtime.h>
#include <cuda_bf16.h>
#include <math.h>
#include <stdint.h>

// Problem constants
#define B_   2
#define T_   2048
#define E_   2048
#define H_   16
#define HKV_ 4
#define D_   128
#define ROWS (B_ * T_)          // 4096
#define QCOLS (H_ * D_)         // 2048
#define KCOLS (HKV_ * D_)       // 512

// ---------------------------------------------------------------------------
// Scratch (allocation-free: device globals)
// ---------------------------------------------------------------------------
__device__ __align__(1024) float g_xr [(size_t)ROWS * E_];
__device__ __align__(1024) float g_Wq [(size_t)E_ * QCOLS];
__device__ __align__(1024) float g_Wk [(size_t)E_ * KCOLS];
__device__ __align__(1024) float g_Wv [(size_t)E_ * KCOLS];
__device__ __align__(1024) float g_Wo [(size_t)QCOLS * E_];
__device__ __align__(1024) float g_Q  [(size_t)ROWS * QCOLS];
__device__ __align__(1024) float g_K  [(size_t)ROWS * KCOLS];
__device__ __align__(1024) float g_V  [(size_t)ROWS * KCOLS];
__device__ __align__(1024) float g_ctx[(size_t)ROWS * QCOLS];
__device__ __align__(1024) float g_rcos[T_ * 64];
__device__ __align__(1024) float g_rsin[T_ * 64];

// ---------------------------------------------------------------------------
// Helpers
// ---------------------------------------------------------------------------
__device__ __forceinline__ float rna_tf32(float x) {
    uint32_t y;
    asm("cvt.rna.tf32.f32 %0, %1;" : "=r"(y) : "f"(x));
    return __uint_as_float(y);
}
__device__ __forceinline__ uint32_t smem_u32(const void* p) {
    uint32_t a;
    asm("{ .reg .u64 t; cvta.to.shared.u64 t, %1; cvt.u32.u64 %0, t; }" : "=r"(a) : "l"(p));
    return a;
}
__device__ __forceinline__ void cp_async16(uint32_t saddr, const void* gptr) {
    asm volatile("cp.async.cg.shared.global [%0], [%1], 16;" :: "r"(saddr), "l"(gptr));
}
#define CP_COMMIT() asm volatile("cp.async.commit_group;" ::: "memory")
#define CP_WAIT(n)  asm volatile("cp.async.wait_group %0;" :: "n"(n) : "memory")

__device__ __forceinline__ void mma_tf32(float* c, const uint32_t* a, const uint32_t* b) {
    asm volatile(
        "mma.sync.aligned.m16n8k8.row.col.f32.tf32.tf32.f32 "
        "{%0,%1,%2,%3}, {%4,%5,%6,%7}, {%8,%9}, {%0,%1,%2,%3};"
        : "+f"(c[0]), "+f"(c[1]), "+f"(c[2]), "+f"(c[3])
        : "r"(a[0]), "r"(a[1]), "r"(a[2]), "r"(a[3]), "r"(b[0]), "r"(b[1]));
}

// ---------------------------------------------------------------------------
// Rope cos/sin table (double-precision source, fp32 table).
// ---------------------------------------------------------------------------
__global__ void rope_table(float* __restrict__ ct, float* __restrict__ st) {
    int idx = blockIdx.x * blockDim.x + threadIdx.x;
    if (idx >= T_ * 64) return;
    int t = idx >> 6, i = idx & 63;
    double w = pow(10000.0, -(double)i / 64.0);
    double ds, dc;
    sincos((double)t * w, &ds, &dc);
    ct[idx] = (float)dc;
    st[idx] = (float)ds;
}

// ---------------------------------------------------------------------------
// One-shot prep: tf32-RN rounding copy of all 5 operand tensors.
// ---------------------------------------------------------------------------
#define P_S0 (ROWS * E_ / 4)
#define P_S1 (P_S0 + E_ * QCOLS / 4)
#define P_S2 (P_S1 + E_ * KCOLS / 4)
#define P_S3 (P_S2 + E_ * KCOLS / 4)
#define P_S4 (P_S3 + QCOLS * E_ / 4)

__global__ void prep_all(const float* __restrict__ x,  const float* __restrict__ wq,
                         const float* __restrict__ wk, const float* __restrict__ wv,
                         const float* __restrict__ wo,
                         float* xr, float* wqr, float* wkr, float* wvr, float* wor) {
    int idx = blockIdx.x * blockDim.x + threadIdx.x;
    const float4* in; float4* out; int j;
    if      (idx < P_S0) { in = (const float4*)x;  out = (float4*)xr;  j = idx; }
    else if (idx < P_S1) { in = (const float4*)wq; out = (float4*)wqr; j = idx - P_S0; }
    else if (idx < P_S2) { in = (const float4*)wk; out = (float4*)wkr; j = idx - P_S1; }
    else if (idx < P_S3) { in = (const float4*)wv; out = (float4*)wvr; j = idx - P_S2; }
    else if (idx < P_S4) { in = (const float4*)wo; out = (float4*)wor; j = idx - P_S3; }
    else return;
    float4 v = in[j];
    v.x = rna_tf32(v.x); v.y = rna_tf32(v.y); v.z = rna_tf32(v.z); v.w = rna_tf32(v.w);
    out[j] = v;
}

// ---------------------------------------------------------------------------
// TF32 mma.sync GEMM, 3-way block dispatch, 2-stage cp.async, 2 CTAs/SM.
// C[M,N] = A[M,K] @ B[K,N]. Tile 128x128x32, 256 threads (8 warps, 4x2).
// Segment s covers blockIdx.x in [start_s, start_s + nblk_s): own B, C, N, mode.
// mode: 0 plain store, 1 round, 2 rope+scale+round (Q), 3 rope+round (K).
// ---------------------------------------------------------------------------
#define GBM 128
#define GBN 128
#define GBK 32
#define GAST 36
#define GBST 136
#define GSTAGES 2
#define GA_FLOATS (GBM * GAST)
#define GB_FLOATS (GBK * GBST)
#define GSTAGE_FLOATS (GA_FLOATS + GB_FLOATS)
#define GSMEM_BYTES (GSTAGES * GSTAGE_FLOATS * 4)   // 71680

__global__ __launch_bounds__(256, 2) void gemm_mma(
    const float* __restrict__ A,
    const float* __restrict__ B1, float* __restrict__ C1, int mode1, int nblk1, int N1,
    const float* __restrict__ B2, float* __restrict__ C2, int mode2, int nblk2, int N2,
    const float* __restrict__ B3, float* __restrict__ C3, int mode3, int N3,
    int K, const float* __restrict__ ct, const float* __restrict__ st)
{
    extern __shared__ __align__(16) float smem[];
    const int tid = threadIdx.x;
    const int wid = tid >> 5, lane = tid & 31;
    const int warpM = wid & 3, warpN = wid >> 2;
    const int bx = blockIdx.x;

    const float* Bw; float* C; int mode, n0, N;
    if (bx < nblk1)              { Bw = B1; C = C1; mode = mode1; N = N1; n0 = bx * GBN; }
    else if (bx < nblk1 + nblk2) { Bw = B2; C = C2; mode = mode2; N = N2; n0 = (bx - nblk1) * GBN; }
    else                         { Bw = B3; C = C3; mode = mode3; N = N3; n0 = (bx - nblk1 - nblk2) * GBN; }

    const int m0 = blockIdx.y * GBM;
    const int nch = K / GBK;
    const int lr = lane >> 2, lc = lane & 3;

    float acc[2][8][4];
#pragma unroll
    for (int i = 0; i < 2; i++)
#pragma unroll
        for (int j = 0; j < 8; j++)
#pragma unroll
            for (int q = 0; q < 4; q++) acc[i][j][q] = 0.f;

    auto load_chunk = [&](int c, int s) {
        float* As = smem + s * GSTAGE_FLOATS;
        float* Bs = As + GA_FLOATS;
        const uint32_t as_base = smem_u32(As);
        const uint32_t bs_base = smem_u32(Bs);
#pragma unroll
        for (int i = 0; i < 4; i++) {
            int ci = tid + i * 256;
            int row = ci >> 3, ch = ci & 7;
            cp_async16(as_base + (row * GAST + ch * 4) * 4,
                       A + (size_t)(m0 + row) * K + c * GBK + ch * 4);
        }
#pragma unroll
        for (int i = 0; i < 4; i++) {
            int ci = tid + i * 256;
            int row = ci >> 5, ch = ci & 31;
            cp_async16(bs_base + (row * GBST + ch * 4) * 4,
                       Bw + (size_t)(c * GBK + row) * N + n0 + ch * 4);
        }
    };

    load_chunk(0, 0);
    CP_COMMIT();

    for (int c = 0; c < nch; c++) {
        CP_WAIT(0);
        __syncthreads();

        int pc = c + 1;
        if (pc < nch) { load_chunk(pc, pc & 1); CP_COMMIT(); }

        const float* As = smem + (c & 1) * GSTAGE_FLOATS;
        const float* Bs = As + GA_FLOATS;
        const uint32_t* Asu = (const uint32_t*)As;
        const uint32_t* Bsu = (const uint32_t*)Bs;

#pragma unroll
        for (int kk = 0; kk < 4; kk++) {
            uint32_t afr[2][4], bfr[8][2];
#pragma unroll
            for (int mt = 0; mt < 2; mt++) {
                int row = warpM * 32 + mt * 16 + lr;
                int col = kk * 8 + lc;
                afr[mt][0] = Asu[row * GAST + col];
                afr[mt][1] = Asu[(row + 8) * GAST + col];
                afr[mt][2] = Asu[row * GAST + col + 4];
                afr[mt][3] = Asu[(row + 8) * GAST + col + 4];
            }
#pragma unroll
            for (int nt = 0; nt < 8; nt++) {
                int n = warpN * 64 + nt * 8 + lr;
                int k = kk * 8 + lc;
                bfr[nt][0] = Bsu[k * GBST + n];
                bfr[nt][1] = Bsu[(k + 4) * GBST + n];
            }
#pragma unroll
            for (int mt = 0; mt < 2; mt++)
#pragma unroll
                for (int nt = 0; nt < 8; nt++)
                    mma_tf32(acc[mt][nt], afr[mt], bfr[nt]);
        }
        __syncthreads();
    }

    // ---- fused epilogue ----
#pragma unroll
    for (int mt = 0; mt < 2; mt++) {
        int rbase = m0 + warpM * 32 + mt * 16 + lr;
#pragma unroll
        for (int nt = 0; nt < 8; nt++) {
            int cbase = n0 + warpN * 64 + nt * 8 + lc * 2;
            float4 v = make_float4(acc[mt][nt][0], acc[mt][nt][1],
                                   acc[mt][nt][2], acc[mt][nt][3]);
            if (mode >= 2) {
                int i  = (cbase & 127) >> 1;
                int t0 = rbase & (T_ - 1);
                int t1 = (rbase + 8) & (T_ - 1);
                float c0 = ct[(t0 << 6) + i], s0 = st[(t0 << 6) + i];
                float c1 = ct[(t1 << 6) + i], s1 = st[(t1 << 6) + i];
                float scale = (mode == 2) ? 0.08838834764831845f : 1.0f;
                float x0 = (v.x * c0 - v.y * s0) * scale;
                float y0 = (v.x * s0 + v.y * c0) * scale;
                float x1 = (v.z * c1 - v.w * s1) * scale;
                float y1 = (v.z * s1 + v.w * c1) * scale;
                v = make_float4(rna_tf32(x0), rna_tf32(y0), rna_tf32(x1), rna_tf32(y1));
            } else if (mode == 1) {
                v.x = rna_tf32(v.x); v.y = rna_tf32(v.y);
                v.z = rna_tf32(v.z); v.w = rna_tf32(v.w);
            }
            *(float2*)(C + (size_t)rbase * N + cbase)       = make_float2(v.x, v.y);
            *(float2*)(C + (size_t)(rbase + 8) * N + cbase) = make_float2(v.z, v.w);
        }
    }
}

// ---------------------------------------------------------------------------
// Causal flash attention with tf32 mma.sync (unchanged).
// ---------------------------------------------------------------------------
#define FBM 128
#define FBN 64
#define KST 132
#define VST 136
#define PST 68
#define KS_FLOATS (2 * 64 * KST)
#define VS_FLOATS (2 * 64 * VST)
#define PS_FLOATS (8 * 16 * PST)
#define FA_SMEM_BYTES ((KS_FLOATS + VS_FLOATS + PS_FLOATS) * 4)

__global__ __launch_bounds__(256, 1) void flash_mma(const float* __restrict__ Q,
                                                    const float* __restrict__ Km,
                                                    const float* __restrict__ Vm,
                                                    float* __restrict__ ctx) {
    extern __shared__ __align__(16) float sm[];
    float* KsB = sm;
    float* VsB = sm + KS_FLOATS;
    float* PsB = VsB + VS_FLOATS;

    const int tid = threadIdx.x;
    const int wid = tid >> 5, lane = tid & 31;
    const int lr = lane >> 2, lc = lane & 3;
    const int m0 = (int)(gridDim.x - 1 - blockIdx.x) * FBM;
    const int h = blockIdx.y, b = blockIdx.z;
    const int kvh = h >> 2;

    float* Psw = PsB + wid * 16 * PST;
    uint32_t* Psu = (uint32_t*)Psw;

    uint32_t qa[16][4];
    {
        const float* qsrc = Q + (size_t)(b * T_ + m0 + wid * 16) * QCOLS + h * 128;
#pragma unroll
        for (int hh = 0; hh < 2; hh++) {
#pragma unroll
            for (int i = 0; i < 8; i++) {
                int task = lane + i * 32;
                int row = task >> 4, c4 = task & 15;
                float4 v = *(const float4*)(qsrc + (size_t)row * QCOLS + hh * 64 + c4 * 4);
                *(float4*)&Psw[row * PST + c4 * 4] = v;
            }
            __syncwarp();
#pragma unroll
            for (int k8 = 0; k8 < 8; k8++) {
                int kk = hh * 8 + k8;
                qa[kk][0] = Psu[lr * PST + k8 * 8 + lc];
                qa[kk][1] = Psu[(lr + 8) * PST + k8 * 8 + lc];
                qa[kk][2] = Psu[lr * PST + k8 * 8 + lc + 4];
                qa[kk][3] = Psu[(lr + 8) * PST + k8 * 8 + lc + 4];
            }
            __syncwarp();
        }
    }

    float oacc[16][4];
#pragma unroll
    for (int i = 0; i < 16; i++)
#pragma unroll
        for (int q = 0; q < 4; q++) oacc[i][q] = 0.f;
    float m_i[2] = {-1e30f, -1e30f};
    float l_i[2] = {0.f, 0.f};

    const int ntiles = m0 / 64 + 2;

    auto load_kv = [&](int t, int stg) {
        const float* kb = Km + (size_t)(b * T_ + t * 64) * KCOLS + kvh * 128;
        const float* vb = Vm + (size_t)(b * T_ + t * 64) * KCOLS + kvh * 128;
        uint32_t ka = smem_u32(KsB + stg * 64 * KST);
        uint32_t va = smem_u32(VsB + stg * 64 * VST);
#pragma unroll
        for (int i = 0; i < 8; i++) {
            int task = tid + i * 256;
            int row = task >> 5, ch = task & 31;
            cp_async16(ka + (row * KST + ch * 4) * 4, kb + (size_t)row * KCOLS + ch * 4);
        }
#pragma unroll
        for (int i = 0; i < 8; i++) {
            int task = tid + i * 256;
            int row = task >> 5, ch = task & 31;
            cp_async16(va + (row * VST + ch * 4) * 4, vb + (size_t)row * KCOLS + ch * 4);
        }
    };

    load_kv(0, 0);
    CP_COMMIT();

    for (int t = 0; t < ntiles; t++) {
        if (t + 1 < ntiles) { load_kv(t + 1, (t + 1) & 1); CP_COMMIT(); CP_WAIT(1); }
        else                { CP_WAIT(0); }
        __syncthreads();

        const uint32_t* Ksu = (const uint32_t*)(KsB + (t & 1) * 64 * KST);
        const uint32_t* Vsu = (const uint32_t*)(VsB + (t & 1) * 64 * VST);

        float sacc[8][4];
#pragma unroll
        for (int nt = 0; nt < 8; nt++)
#pragma unroll
            for (int q = 0; q < 4; q++) sacc[nt][q] = 0.f;

#pragma unroll
        for (int kk = 0; kk < 16; kk++) {
            uint32_t bfr[8][2];
#pragma unroll
            for (int nt = 0; nt < 8; nt++) {
                bfr[nt][0] = Ksu[(nt * 8 + lr) * KST + kk * 8 + lc];
                bfr[nt][1] = Ksu[(nt * 8 + lr) * KST + kk * 8 + lc + 4];
            }
#pragma unroll
            for (int nt = 0; nt < 8; nt++)
                mma_tf32(sacc[nt], qa[kk], bfr[nt]);
        }

        const int row0g = m0 + wid * 16 + lr;
        const int row1g = row0g + 8;
        if (t * 64 + 63 > m0 + wid * 16) {
#pragma unroll
            for (int nt = 0; nt < 8; nt++) {
                int colg = t * 64 + nt * 8 + 2 * lc;
                if (colg     > row0g) sacc[nt][0] = -1e30f;
                if (colg + 1 > row0g) sacc[nt][1] = -1e30f;
                if (colg     > row1g) sacc[nt][2] = -1e30f;
                if (colg + 1 > row1g) sacc[nt][3] = -1e30f;
            }
        }

        float rmax0 = -1e30f, rmax1 = -1e30f;
#pragma unroll
        for (int nt = 0; nt < 8; nt++) {
            rmax0 = fmaxf(rmax0, fmaxf(sacc[nt][0], sacc[nt][1]));
            rmax1 = fmaxf(rmax1, fmaxf(sacc[nt][2], sacc[nt][3]));
        }
        rmax0 = fmaxf(rmax0, __shfl_xor_sync(0xffffffffu, rmax0, 1));
        rmax0 = fmaxf(rmax0, __shfl_xor_sync(0xffffffffu, rmax0, 2));
        rmax1 = fmaxf(rmax1, __shfl_xor_sync(0xffffffffu, rmax1, 1));
        rmax1 = fmaxf(rmax1, __shfl_xor_sync(0xffffffffu, rmax1, 2));

        float mnew0 = fmaxf(m_i[0], rmax0);
        float mnew1 = fmaxf(m_i[1], rmax1);
        float alpha0 = __expf(m_i[0] - mnew0);
        float alpha1 = __expf(m_i[1] - mnew1);

        float rsum0 = 0.f, rsum1 = 0.f;
#pragma unroll
        for (int nt = 0; nt < 8; nt++) {
            float p0 = rna_tf32(__expf(sacc[nt][0] - mnew0));
            float p1 = rna_tf32(__expf(sacc[nt][1] - mnew0));
            float p2 = rna_tf32(__expf(sacc[nt][2] - mnew1));
            float p3 = rna_tf32(__expf(sacc[nt][3] - mnew1));
            rsum0 += p0 + p1;
            rsum1 += p2 + p3;
            *(float2*)&Psw[lr * PST + nt * 8 + 2 * lc]       = make_float2(p0, p1);
            *(float2*)&Psw[(lr + 8) * PST + nt * 8 + 2 * lc] = make_float2(p2, p3);
        }
        rsum0 += __shfl_xor_sync(0xffffffffu, rsum0, 1);
        rsum0 += __shfl_xor_sync(0xffffffffu, rsum0, 2);
        rsum1 += __shfl_xor_sync(0xffffffffu, rsum1, 1);
        rsum1 += __shfl_xor_sync(0xffffffffu, rsum1, 2);

        l_i[0] = l_i[0] * alpha0 + rsum0;
        l_i[1] = l_i[1] * alpha1 + rsum1;
        m_i[0] = mnew0;
        m_i[1] = mnew1;
#pragma unroll
        for (int nt = 0; nt < 16; nt++) {
            oacc[nt][0] *= alpha0; oacc[nt][1] *= alpha0;
            oacc[nt][2] *= alpha1; oacc[nt][3] *= alpha1;
        }
        __syncwarp();

#pragma unroll
        for (int kk = 0; kk < 8; kk++) {
            uint32_t pa[4];
            pa[0] = Psu[lr * PST + kk * 8 + lc];
            pa[1] = Psu[(lr + 8) * PST + kk * 8 + lc];
            pa[2] = Psu[lr * PST + kk * 8 + lc + 4];
            pa[3] = Psu[(lr + 8) * PST + kk * 8 + lc + 4];
#pragma unroll
            for (int nt = 0; nt < 16; nt++) {
                uint32_t bfr[2];
                bfr[0] = Vsu[(kk * 8 + lc) * VST + nt * 8 + lr];
                bfr[1] = Vsu[(kk * 8 + lc + 4) * VST + nt * 8 + lr];
                mma_tf32(oacc[nt], pa, bfr);
            }
        }
        __syncwarp();
        __syncthreads();
    }

    float inv0 = 1.0f / l_i[0];
    float inv1 = 1.0f / l_i[1];
    const int row0g = m0 + wid * 16 + lr;
    float* c0 = ctx + (size_t)(b * T_ + row0g) * QCOLS + h * 128;
    float* c1 = ctx + (size_t)(b * T_ + row0g + 8) * QCOLS + h * 128;
#pragma unroll
    for (int nt = 0; nt < 16; nt++) {
        int col = nt * 8 + 2 * lc;
        *(float2*)(c0 + col) = make_float2(rna_tf32(oacc[nt][0] * inv0),
                                           rna_tf32(oacc[nt][1] * inv0));
        *(float2*)(c1 + col) = make_float2(rna_tf32(oacc[nt][2] * inv1),
                                           rna_tf32(oacc[nt][3] * inv1));
    }
}

// ---------------------------------------------------------------------------
// Host
// ---------------------------------------------------------------------------
extern "C" void kernel_launch(void* const* d_in, const int* in_sizes, int n_in,
                              void* d_out, int out_size) {
    const float* x    = (const float*)d_in[0];
    const float* Wq   = (const float*)d_in[1];
    const float* Wk   = (const float*)d_in[2];
    const float* Wv   = (const float*)d_in[3];
    const float* Wout = (const float*)d_in[4];
    float* out = (float*)d_out;

    float *xr, *Wqr, *Wkr, *Wvr, *Wor, *Qb, *Kb, *Vb, *Cb, *ctab, *stab;
    cudaGetSymbolAddress((void**)&xr,  g_xr);
    cudaGetSymbolAddress((void**)&Wqr, g_Wq);
    cudaGetSymbolAddress((void**)&Wkr, g_Wk);
    cudaGetSymbolAddress((void**)&Wvr, g_Wv);
    cudaGetSymbolAddress((void**)&Wor, g_Wo);
    cudaGetSymbolAddress((void**)&Qb,  g_Q);
    cudaGetSymbolAddress((void**)&Kb,  g_K);
    cudaGetSymbolAddress((void**)&Vb,  g_V);
    cudaGetSymbolAddress((void**)&Cb,  g_ctx);
    cudaGetSymbolAddress((void**)&ctab, g_rcos);
    cudaGetSymbolAddress((void**)&stab, g_rsin);

    cudaFuncSetAttribute(gemm_mma, cudaFuncAttributeMaxDynamicSharedMemorySize, GSMEM_BYTES);
    cudaFuncSetAttribute(flash_mma, cudaFuncAttributeMaxDynamicSharedMemorySize, FA_SMEM_BYTES);

    // 1) prep: round all operands to tf32-RN
    prep_all<<<(P_S4 + 255) / 256, 256>>>(x, Wq, Wk, Wv, Wout, xr, Wqr, Wkr, Wvr, Wor);

    // 2) rope table
    rope_table<<<(T_ * 64 + 255) / 256, 256>>>(ctab, stab);

    // 3) Q + K + V projections in ONE launch (grid.x = 16 + 4 + 4 = 24)
    gemm_mma<<<dim3(24, ROWS / GBM), 256, GSMEM_BYTES>>>(
        xr,
        Wqr, Qb, 2, QCOLS / GBN, QCOLS,     // Q: rope + 1/sqrt(D) + round
        Wkr, Kb, 3, KCOLS / GBN, KCOLS,     // K: rope + round
        Wvr, Vb, 1, KCOLS,                  // V: round
        E_, ctab, stab);

    // 4) attention
    flash_mma<<<dim3(T_ / FBM, H_, B_), 256, FA_SMEM_BYTES>>>(Qb, Kb, Vb, Cb);

    // 5) output projection
    gemm_mma<<<dim3(E_ / GBN, ROWS / GBM), 256, GSMEM_BYTES>>>(
        Cb,
        Wor, out, 0, E_ / GBN, E_,
        Wor, out, 0, 0, E_,
        Wor, out, 0, E_,
        QCOLS, ctab, stab);
}